// round 7
// baseline (speedup 1.0000x reference)
#include <cuda_runtime.h>
#include <cuda_bf16.h>
#include <math.h>
#include <stdint.h>

// Problem constants
#define SS  4
#define NN  32768
#define DD  256
#define KK  512
#define NHH 4
#define HDD 64
#define FF  1024
#define QKVW 768

// ---------------- scratch (device globals; no runtime allocation) ----------------
__device__ float g_x   [SS*KK*DD];
__device__ int   g_cnt [SS*KK];
__device__ int   g_off [SS*KK];
__device__ int   g_cur [SS*KK];
__device__ int   g_nlist[SS*NN];
__device__ float g_y   [SS*KK*DD];
__device__ float g_qkv [SS*KK*QKVW];
__device__ float g_kv  [SS*NHH*HDD*HDD];
__device__ float g_ksum[SS*NHH*HDD];
__device__ float g_attn[SS*KK*DD];
__device__ float g_x2  [SS*KK*DD];
__device__ float g_h   [SS*KK*FF];
__device__ float g_p2  [SS*KK*DD];
__device__ float g_bqkv[QKVW];

// bf16 hi/lo split weights, all [n][k] layout
__device__ __nv_bfloat16 g_wqkvh[QKVW*DD], g_wqkvl[QKVW*DD];
__device__ __nv_bfloat16 g_woh [DD*DD],   g_wol [DD*DD];
__device__ __nv_bfloat16 g_f1h [FF*DD],   g_f1l [FF*DD];
__device__ __nv_bfloat16 g_f2h [DD*FF],   g_f2l [DD*FF];
__device__ __nv_bfloat16 g_p2h [DD*DD],   g_p2l [DD*DD];   // mW1[256:512]
__device__ __nv_bfloat16 g_w1h [DD*DD],   g_w1l [DD*DD];   // mW1[0:256]
__device__ __nv_bfloat16 g_w2h [DD*DD],   g_w2l [DD*DD];   // mW2

// ---------------- small device helpers ----------------
__device__ __forceinline__ float geluf(float x) {
    return 0.5f * x * (1.0f + erff(x * 0.70710678118654752440f));
}
__device__ __forceinline__ float phif(float x) {   // elu(x)+1
    return x > 0.0f ? x + 1.0f : expf(x);
}
__device__ __forceinline__ uint32_t pack_bf2(float a, float b) {
    __nv_bfloat162 t = __floats2bfloat162_rn(a, b);
    return *(uint32_t*)&t;
}
__device__ __forceinline__ float bflo(uint32_t p) {
    __nv_bfloat162 b = *(__nv_bfloat162*)&p; return __bfloat162float(b.x);
}
__device__ __forceinline__ float bfhi(uint32_t p) {
    __nv_bfloat162 b = *(__nv_bfloat162*)&p; return __bfloat162float(b.y);
}
__device__ __forceinline__ uint32_t smem_u32(const void* p) {
    uint32_t a;
    asm("{ .reg .u64 t; cvta.to.shared.u64 t, %1; cvt.u32.u64 %0, t; }" : "=r"(a) : "l"(p));
    return a;
}
#define LDSM_X4(r0, r1, r2, r3, addr) \
    asm volatile("ldmatrix.sync.aligned.m8n8.x4.shared.b16 {%0,%1,%2,%3}, [%4];" \
                 : "=r"(r0), "=r"(r1), "=r"(r2), "=r"(r3) : "r"(addr))
#define MMA_BF16(d, a, b) \
    asm volatile("mma.sync.aligned.m16n8k16.row.col.f32.bf16.bf16.f32 " \
                 "{%0,%1,%2,%3},{%4,%5,%6,%7},{%8,%9},{%0,%1,%2,%3};" \
                 : "+f"((d)[0]), "+f"((d)[1]), "+f"((d)[2]), "+f"((d)[3]) \
                 : "r"((a)[0]), "r"((a)[1]), "r"((a)[2]), "r"((a)[3]), \
                   "r"((b)[0]), "r"((b)[1]))

// ---------------- pooling (count-sort, no fp32 atomics) ----------------
__global__ void k_zero_cnt() {
    int i = blockIdx.x * blockDim.x + threadIdx.x;
    if (i < SS*KK) g_cnt[i] = 0;
}

__global__ void k_count(const int* __restrict__ pid) {
    int b = blockIdx.x * blockDim.x + threadIdx.x;
    int s = b >> 15;
    atomicAdd(&g_cnt[s*KK + pid[b]], 1);
}

__global__ void k_scan() {
    __shared__ int part[256];
    int t = threadIdx.x;
    int base = t * 8;
    int loc[8];
    int sum = 0;
    #pragma unroll
    for (int i = 0; i < 8; i++) { loc[i] = sum; sum += g_cnt[base + i]; }
    part[t] = sum;
    __syncthreads();
    #pragma unroll
    for (int off = 1; off < 256; off <<= 1) {
        int v = (t >= off) ? part[t - off] : 0;
        __syncthreads();
        part[t] += v;
        __syncthreads();
    }
    int prev = (t > 0) ? part[t - 1] : 0;
    #pragma unroll
    for (int i = 0; i < 8; i++) {
        g_off[base + i] = prev + loc[i];
        g_cur[base + i] = prev + loc[i];
    }
}

__global__ void k_scatter(const int* __restrict__ pid) {
    int b = blockIdx.x * blockDim.x + threadIdx.x;
    int s = b >> 15;
    int pos = atomicAdd(&g_cur[s*KK + pid[b]], 1);
    g_nlist[pos] = b;
}

__global__ __launch_bounds__(256) void k_patchsum(const float* __restrict__ H) {
    int r = blockIdx.x;
    int d = threadIdx.x;
    int cnt = g_cnt[r];
    int off = g_off[r];
    float a0 = 0.f, a1 = 0.f, a2 = 0.f, a3 = 0.f;
    int i = 0;
    for (; i + 4 <= cnt; i += 4) {
        int n0 = g_nlist[off+i],   n1 = g_nlist[off+i+1];
        int n2 = g_nlist[off+i+2], n3 = g_nlist[off+i+3];
        a0 += __ldg(&H[(size_t)n0*DD + d]);
        a1 += __ldg(&H[(size_t)n1*DD + d]);
        a2 += __ldg(&H[(size_t)n2*DD + d]);
        a3 += __ldg(&H[(size_t)n3*DD + d]);
    }
    for (; i < cnt; i++) a0 += __ldg(&H[(size_t)g_nlist[off+i]*DD + d]);
    float sum = (a0 + a1) + (a2 + a3);
    float inv = (cnt > 0) ? (1.0f / (float)cnt) : 0.0f;
    g_x[(size_t)r*DD + d] = sum * inv;
}

// ---------------- weight prep ----------------
__global__ void k_prep_w(const float* __restrict__ Wq, const float* __restrict__ Wk,
                         const float* __restrict__ Wv, const float* __restrict__ bq,
                         const float* __restrict__ bk, const float* __restrict__ bv,
                         const float* __restrict__ Wo, const float* __restrict__ fW1,
                         const float* __restrict__ fW2, const float* __restrict__ mW1,
                         const float* __restrict__ mW2) {
    int r = blockIdx.x, t = threadIdx.x;
    if (r < 768) {
        int n = r;
        float v = (n < 256) ? Wq[t*DD + n] : (n < 512) ? Wk[t*DD + (n-256)] : Wv[t*DD + (n-512)];
        __nv_bfloat16 h = __float2bfloat16(v);
        g_wqkvh[n*DD + t] = h;
        g_wqkvl[n*DD + t] = __float2bfloat16(v - __bfloat162float(h));
        if (t == 0) g_bqkv[n] = (n < 256) ? bq[n] : (n < 512) ? bk[n-256] : bv[n-512];
    } else if (r < 1024) {
        int n = r - 768;
        float v = Wo[t*DD + n];
        __nv_bfloat16 h = __float2bfloat16(v);
        g_woh[n*DD + t] = h;
        g_wol[n*DD + t] = __float2bfloat16(v - __bfloat162float(h));
    } else if (r < 2048) {
        int n = r - 1024;
        float v = fW1[t*FF + n];
        __nv_bfloat16 h = __float2bfloat16(v);
        g_f1h[n*DD + t] = h;
        g_f1l[n*DD + t] = __float2bfloat16(v - __bfloat162float(h));
    } else if (r < 2304) {
        int n = r - 2048;
        #pragma unroll
        for (int kk = 0; kk < 4; kk++) {
            int k = t + kk*256;
            float v = fW2[k*DD + n];
            __nv_bfloat16 h = __float2bfloat16(v);
            g_f2h[n*FF + k] = h;
            g_f2l[n*FF + k] = __float2bfloat16(v - __bfloat162float(h));
        }
    } else if (r < 2560) {
        int n = r - 2304;
        float v = mW1[(256 + t)*DD + n];
        __nv_bfloat16 h = __float2bfloat16(v);
        g_p2h[n*DD + t] = h;
        g_p2l[n*DD + t] = __float2bfloat16(v - __bfloat162float(h));
    } else if (r < 2816) {
        int n = r - 2560;
        float v = mW1[t*DD + n];
        __nv_bfloat16 h = __float2bfloat16(v);
        g_w1h[n*DD + t] = h;
        g_w1l[n*DD + t] = __float2bfloat16(v - __bfloat162float(h));
    } else {
        int n = r - 2816;
        float v = mW2[t*DD + n];
        __nv_bfloat16 h = __float2bfloat16(v);
        g_w2h[n*DD + t] = h;
        g_w2l[n*DD + t] = __float2bfloat16(v - __bfloat162float(h));
    }
}

// ---------------- layer norm ----------------
__global__ void k_ln(const float* __restrict__ in, const float* __restrict__ gw,
                     const float* __restrict__ bw, float* __restrict__ out) {
    int r = blockIdx.x, d = threadIdx.x;
    float v = in[(size_t)r*DD + d];
    __shared__ float s1[8], s2[8];
    __shared__ float smu, sri;
    float a = v, b = v * v;
    #pragma unroll
    for (int o = 16; o > 0; o >>= 1) {
        a += __shfl_down_sync(0xffffffffu, a, o);
        b += __shfl_down_sync(0xffffffffu, b, o);
    }
    if ((d & 31) == 0) { s1[d >> 5] = a; s2[d >> 5] = b; }
    __syncthreads();
    if (d == 0) {
        float sa = 0.f, sb = 0.f;
        #pragma unroll
        for (int i = 0; i < 8; i++) { sa += s1[i]; sb += s2[i]; }
        float m   = sa * (1.0f / DD);
        float var = sb * (1.0f / DD) - m * m;
        smu = m; sri = rsqrtf(var + 1e-5f);
    }
    __syncthreads();
    out[(size_t)r*DD + d] = (v - smu) * sri * gw[d] + bw[d];
}

__global__ __launch_bounds__(256) void k_kvsum() {
    int b = blockIdx.x;
    int s = b >> 2, h = b & 3;
    int t = threadIdx.x, tx = t & 15, ty = t >> 4;
    __shared__ float ks[8][64], vs[8][64];
    float acc[4][4] = {};
    float ksl = 0.0f;
    const float* kp = g_qkv + (size_t)s*KK*QKVW + 256 + h*HDD;
    const float* vp = g_qkv + (size_t)s*KK*QKVW + 512 + h*HDD;

    for (int k0 = 0; k0 < KK; k0 += 8) {
        #pragma unroll
        for (int u = 0; u < 2; u++) {
            int idx = t + u*256; int i = idx >> 6, d = idx & 63;
            ks[i][d] = kp[(size_t)(k0 + i)*QKVW + d];
            vs[i][d] = vp[(size_t)(k0 + i)*QKVW + d];
        }
        __syncthreads();
        if (t < 64) {
            #pragma unroll
            for (int i = 0; i < 8; i++) ksl += ks[i][t];
        }
        #pragma unroll
        for (int i = 0; i < 8; i++) {
            float kd[4], ve[4];
            #pragma unroll
            for (int j = 0; j < 4; j++) { kd[j] = ks[i][ty*4+j]; ve[j] = vs[i][tx*4+j]; }
            #pragma unroll
            for (int a = 0; a < 4; a++)
                #pragma unroll
                for (int c = 0; c < 4; c++)
                    acc[a][c] += kd[a] * ve[c];
        }
        __syncthreads();
    }
    if (t < 64) g_ksum[(size_t)b*64 + t] = ksl;
    #pragma unroll
    for (int a = 0; a < 4; a++)
        #pragma unroll
        for (int c = 0; c < 4; c++)
            g_kv[((size_t)b*64 + ty*4 + a)*64 + tx*4 + c] = acc[a][c];
}

__global__ void k_attn() {
    int r = blockIdx.x;
    int s = r / KK;
    int t = threadIdx.x;
    __shared__ float qs[256];
    qs[t] = g_qkv[(size_t)r*QKVW + t];
    __syncthreads();
    int h = t >> 6, e = t & 63;
    const float* kvp = g_kv   + (size_t)(s*NHH + h)*HDD*HDD;
    const float* ksp = g_ksum + (size_t)(s*NHH + h)*HDD;
    float num = 0.f, den = 0.f;
    #pragma unroll 8
    for (int d = 0; d < 64; d++) {
        float q = qs[h*64 + d];
        num += q * kvp[d*64 + e];
        den += q * ksp[d];
    }
    g_attn[(size_t)r*DD + t] = num / (den + 1e-6f);
}

// ---- Patch-level tensor-core GEMM (256 threads, 128x128 tile) ----
// modes: 0: +bias; 2: +bias+res; 5: gelu(+bias); 6: qkv epilogue
__global__ __launch_bounds__(256, 2) void k_mma(
    const float* __restrict__ A,
    const __nv_bfloat16* __restrict__ Bh,
    const __nv_bfloat16* __restrict__ Bl,
    float* __restrict__ C, int Kd, int Cld, int mode,
    const float* __restrict__ bias, const float* __restrict__ res)
{
    __shared__ __nv_bfloat16 Ash[128][40];
    __shared__ __nv_bfloat16 Asl[128][40];
    __shared__ __nv_bfloat16 Bsh[128][40];
    __shared__ __nv_bfloat16 Bsl[128][40];

    const int t = threadIdx.x, lane = t & 31, wid = t >> 5;
    const int n0 = blockIdx.x * 128, m0 = blockIdx.y * 128;
    const int wm = (wid & 3) * 32;
    const int wn = (wid >> 2) * 64;

    const uint32_t sAh = smem_u32(Ash), sAl = smem_u32(Asl);
    const uint32_t sBh = smem_u32(Bsh), sBl = smem_u32(Bsl);

    const int a_m = wm + (lane & 15);
    const int a_k = (lane >> 4) << 3;
    const int b_n = wn + ((lane >> 4) << 3) + (lane & 7);
    const int b_k = ((lane >> 3) & 1) << 3;

    float acc[2][8][4] = {};
    const int nchunks = Kd >> 5;

    for (int c = 0; c < nchunks; c++) {
        const int k0 = c * 32;
        #pragma unroll
        for (int i = 0; i < 4; i++) {
            int lin = t + 256 * i;
            int row = lin >> 3, q = lin & 7;
            float4 f = *(const float4*)(A + (size_t)(m0 + row)*Kd + k0 + q*4);
            uint32_t h01 = pack_bf2(f.x, f.y);
            uint32_t h23 = pack_bf2(f.z, f.w);
            uint32_t l01 = pack_bf2(f.x - bflo(h01), f.y - bfhi(h01));
            uint32_t l23 = pack_bf2(f.z - bflo(h23), f.w - bfhi(h23));
            *(uint2*)&Ash[row][q*4] = make_uint2(h01, h23);
            *(uint2*)&Asl[row][q*4] = make_uint2(l01, l23);
        }
        #pragma unroll
        for (int i = 0; i < 2; i++) {
            int lin = t + 256 * i;
            int row = lin >> 2, q = lin & 3;
            *(uint4*)&Bsh[row][q*8] = *(const uint4*)(Bh + (size_t)(n0 + row)*Kd + k0 + q*8);
            *(uint4*)&Bsl[row][q*8] = *(const uint4*)(Bl + (size_t)(n0 + row)*Kd + k0 + q*8);
        }
        __syncthreads();

        #pragma unroll
        for (int kk = 0; kk < 2; kk++) {
            uint32_t ah[2][4], al[2][4];
            #pragma unroll
            for (int mt = 0; mt < 2; mt++) {
                uint32_t offA = (uint32_t)((a_m + mt*16) * 40 + kk*16 + a_k) * 2;
                LDSM_X4(ah[mt][0], ah[mt][1], ah[mt][2], ah[mt][3], sAh + offA);
                LDSM_X4(al[mt][0], al[mt][1], al[mt][2], al[mt][3], sAl + offA);
            }
            #pragma unroll
            for (int g = 0; g < 4; g++) {
                uint32_t offB = (uint32_t)((b_n + g*16) * 40 + kk*16 + b_k) * 2;
                uint32_t bh[2][2], bl[2][2];
                LDSM_X4(bh[0][0], bh[0][1], bh[1][0], bh[1][1], sBh + offB);
                LDSM_X4(bl[0][0], bl[0][1], bl[1][0], bl[1][1], sBl + offB);
                #pragma unroll
                for (int mt = 0; mt < 2; mt++) {
                    #pragma unroll
                    for (int j = 0; j < 2; j++) {
                        float* d = acc[mt][g*2 + j];
                        MMA_BF16(d, ah[mt], bh[j]);
                        MMA_BF16(d, ah[mt], bl[j]);
                        MMA_BF16(d, al[mt], bh[j]);
                    }
                }
            }
        }
        __syncthreads();
    }

    const int lr = lane >> 2;
    const int lc = (lane & 3) * 2;
    #pragma unroll
    for (int mt = 0; mt < 2; mt++) {
        int mrow0 = m0 + wm + mt*16 + lr;
        int mrow1 = mrow0 + 8;
        if (mode == 2) {
            #pragma unroll
            for (int nt = 0; nt < 8; nt++) {
                int col = n0 + wn + nt*8 + lc;
                float2 bv = *(const float2*)(bias + col);
                float2 r0 = *(const float2*)(res + (size_t)mrow0*Cld + col);
                float2 r1 = *(const float2*)(res + (size_t)mrow1*Cld + col);
                float2 o0, o1;
                o0.x = acc[mt][nt][0] + bv.x + r0.x;
                o0.y = acc[mt][nt][1] + bv.y + r0.y;
                o1.x = acc[mt][nt][2] + bv.x + r1.x;
                o1.y = acc[mt][nt][3] + bv.y + r1.y;
                *(float2*)(C + (size_t)mrow0*Cld + col) = o0;
                *(float2*)(C + (size_t)mrow1*Cld + col) = o1;
            }
        } else if (mode == 5) {
            #pragma unroll
            for (int nt = 0; nt < 8; nt++) {
                int col = n0 + wn + nt*8 + lc;
                float2 bv = *(const float2*)(bias + col);
                float2 o0, o1;
                o0.x = geluf(acc[mt][nt][0] + bv.x);
                o0.y = geluf(acc[mt][nt][1] + bv.y);
                o1.x = geluf(acc[mt][nt][2] + bv.x);
                o1.y = geluf(acc[mt][nt][3] + bv.y);
                *(float2*)(C + (size_t)mrow0*Cld + col) = o0;
                *(float2*)(C + (size_t)mrow1*Cld + col) = o1;
            }
        } else if (mode == 6) {
            float mk0 = (g_cnt[mrow0] > 0) ? 1.0f : 0.0f;
            float mk1 = (g_cnt[mrow1] > 0) ? 1.0f : 0.0f;
            #pragma unroll
            for (int nt = 0; nt < 8; nt++) {
                int col = n0 + wn + nt*8 + lc;
                float2 bv = *(const float2*)(bias + col);
                float v00 = acc[mt][nt][0] + bv.x, v01 = acc[mt][nt][1] + bv.y;
                float v10 = acc[mt][nt][2] + bv.x, v11 = acc[mt][nt][3] + bv.y;
                float2 o0, o1;
                if (col < 256) {
                    o0.x = phif(v00); o0.y = phif(v01);
                    o1.x = phif(v10); o1.y = phif(v11);
                } else if (col < 512) {
                    o0.x = phif(v00) * mk0; o0.y = phif(v01) * mk0;
                    o1.x = phif(v10) * mk1; o1.y = phif(v11) * mk1;
                } else {
                    o0.x = v00 * mk0; o0.y = v01 * mk0;
                    o1.x = v10 * mk1; o1.y = v11 * mk1;
                }
                *(float2*)(C + (size_t)mrow0*Cld + col) = o0;
                *(float2*)(C + (size_t)mrow1*Cld + col) = o1;
            }
        } else { // mode 0
            #pragma unroll
            for (int nt = 0; nt < 8; nt++) {
                int col = n0 + wn + nt*8 + lc;
                float2 bv = *(const float2*)(bias + col);
                float2 o0, o1;
                o0.x = acc[mt][nt][0] + bv.x;
                o0.y = acc[mt][nt][1] + bv.y;
                o1.x = acc[mt][nt][2] + bv.x;
                o1.y = acc[mt][nt][3] + bv.y;
                *(float2*)(C + (size_t)mrow0*Cld + col) = o0;
                *(float2*)(C + (size_t)mrow1*Cld + col) = o1;
            }
        }
    }
}

// ---- Fused node MLP: out = hidden@W2^T + b2 + H, hidden = gelu(H@W1a^T + P2[pid]) ----
// 512 threads = 16 warps (4x4), tile 128(M) x 256(N), hidden kept in smem as bf16 hi/lo.
// Dynamic smem layout (bytes):
//   Hh: [128][264] bf16 @ 0        (67584)
//   Hl: [128][264] bf16 @ 67584    (67584)
//   Bh: [256][40]  bf16 @ 135168   (20480)
//   Bl: [256][40]  bf16 @ 155648   (20480)
//   Ah: [128][40]  bf16 @ 176128   (10240)
//   Al: [128][40]  bf16 @ 186368   (10240)
#define NSM_HH 0
#define NSM_HL 67584
#define NSM_BH 135168
#define NSM_BL 155648
#define NSM_AH 176128
#define NSM_AL 186368
#define NSM_TOTAL 196608
#define HLD 264

__global__ __launch_bounds__(512, 1) void k_node(
    const float* __restrict__ H,
    const __nv_bfloat16* __restrict__ W1h, const __nv_bfloat16* __restrict__ W1l,
    const __nv_bfloat16* __restrict__ W2h, const __nv_bfloat16* __restrict__ W2l,
    const float* __restrict__ p2, const int* __restrict__ pid,
    const float* __restrict__ b2, float* __restrict__ out)
{
    extern __shared__ char sm[];
    __nv_bfloat16* Hh  = (__nv_bfloat16*)(sm + NSM_HH);
    __nv_bfloat16* Hl  = (__nv_bfloat16*)(sm + NSM_HL);
    __nv_bfloat16* Bsh = (__nv_bfloat16*)(sm + NSM_BH);
    __nv_bfloat16* Bsl = (__nv_bfloat16*)(sm + NSM_BL);
    __nv_bfloat16* Ash = (__nv_bfloat16*)(sm + NSM_AH);
    __nv_bfloat16* Asl = (__nv_bfloat16*)(sm + NSM_AL);
    const uint32_t sHh = smem_u32(Hh), sHl = smem_u32(Hl);
    const uint32_t sBh = smem_u32(Bsh), sBl = smem_u32(Bsl);
    const uint32_t sAh = smem_u32(Ash), sAl = smem_u32(Asl);

    const int t = threadIdx.x, lane = t & 31, wid = t >> 5;
    const int m0 = blockIdx.x * 128;
    const int wm = (wid & 3) * 32;      // 4 m-groups
    const int wn = (wid >> 2) * 64;     // 4 n-groups -> full N=256

    const int a_m = wm + (lane & 15);
    const int a_k = (lane >> 4) << 3;
    const int b_n = wn + ((lane >> 4) << 3) + (lane & 7);
    const int b_k = ((lane >> 3) & 1) << 3;
    const int lr = lane >> 2;
    const int lc = (lane & 3) * 2;

    float acc[2][8][4] = {};

    // ---------- Phase 1: hidden = gelu(H@W1a^T + p2 gather) ----------
    for (int c = 0; c < 8; c++) {
        const int k0 = c * 32;
        #pragma unroll
        for (int i = 0; i < 2; i++) {
            int lin = t + 512 * i;                 // 1024 float4
            int row = lin >> 3, q = lin & 7;
            float4 f = *(const float4*)(H + (size_t)(m0 + row)*DD + k0 + q*4);
            uint32_t h01 = pack_bf2(f.x, f.y);
            uint32_t h23 = pack_bf2(f.z, f.w);
            uint32_t l01 = pack_bf2(f.x - bflo(h01), f.y - bfhi(h01));
            uint32_t l23 = pack_bf2(f.z - bflo(h23), f.w - bfhi(h23));
            *(uint2*)&Ash[row*40 + q*4] = make_uint2(h01, h23);
            *(uint2*)&Asl[row*40 + q*4] = make_uint2(l01, l23);
        }
        #pragma unroll
        for (int i = 0; i < 2; i++) {
            int lin = t + 512 * i;                 // 1024 uint4 (256 rows x 4)
            int row = lin >> 2, q = lin & 3;
            *(uint4*)&Bsh[row*40 + q*8] = *(const uint4*)(W1h + (size_t)row*DD + k0 + q*8);
            *(uint4*)&Bsl[row*40 + q*8] = *(const uint4*)(W1l + (size_t)row*DD + k0 + q*8);
        }
        __syncthreads();
        #pragma unroll
        for (int kk = 0; kk < 2; kk++) {
            uint32_t ah[2][4], al[2][4];
            #pragma unroll
            for (int mt = 0; mt < 2; mt++) {
                uint32_t offA = (uint32_t)((a_m + mt*16) * 40 + kk*16 + a_k) * 2;
                LDSM_X4(ah[mt][0], ah[mt][1], ah[mt][2], ah[mt][3], sAh + offA);
                LDSM_X4(al[mt][0], al[mt][1], al[mt][2], al[mt][3], sAl + offA);
            }
            #pragma unroll
            for (int g = 0; g < 4; g++) {
                uint32_t offB = (uint32_t)((b_n + g*16) * 40 + kk*16 + b_k) * 2;
                uint32_t bh[2][2], bl[2][2];
                LDSM_X4(bh[0][0], bh[0][1], bh[1][0], bh[1][1], sBh + offB);
                LDSM_X4(bl[0][0], bl[0][1], bl[1][0], bl[1][1], sBl + offB);
                #pragma unroll
                for (int mt = 0; mt < 2; mt++) {
                    #pragma unroll
                    for (int j = 0; j < 2; j++) {
                        float* d = acc[mt][g*2 + j];
                        MMA_BF16(d, ah[mt], bh[j]);
                        MMA_BF16(d, ah[mt], bl[j]);
                        MMA_BF16(d, al[mt], bh[j]);
                    }
                }
            }
        }
        __syncthreads();
    }

    // epilogue 1: gelu(acc + p2 gather) -> smem hidden (bf16 hi/lo)
    {
        int mr0 = wm + lr;          // tile-local rows
        int mr1 = mr0 + 8;
        #pragma unroll
        for (int mt = 0; mt < 2; mt++) {
            int r0 = mr0 + mt*16, r1 = mr1 + mt*16;
            int gm0 = m0 + r0, gm1 = m0 + r1;
            int s0 = gm0 >> 15, s1 = gm1 >> 15;
            const float* p2r0 = p2 + ((size_t)(s0*KK + pid[gm0]))*DD;
            const float* p2r1 = p2 + ((size_t)(s1*KK + pid[gm1]))*DD;
            #pragma unroll
            for (int nt = 0; nt < 8; nt++) {
                int col = wn + nt*8 + lc;
                float v00 = geluf(acc[mt][nt][0] + p2r0[col]);
                float v01 = geluf(acc[mt][nt][1] + p2r0[col+1]);
                float v10 = geluf(acc[mt][nt][2] + p2r1[col]);
                float v11 = geluf(acc[mt][nt][3] + p2r1[col+1]);
                uint32_t h0 = pack_bf2(v00, v01);
                uint32_t l0 = pack_bf2(v00 - bflo(h0), v01 - bfhi(h0));
                uint32_t h1 = pack_bf2(v10, v11);
                uint32_t l1 = pack_bf2(v10 - bflo(h1), v11 - bfhi(h1));
                *(uint32_t*)&Hh[r0*HLD + col] = h0;
                *(uint32_t*)&Hl[r0*HLD + col] = l0;
                *(uint32_t*)&Hh[r1*HLD + col] = h1;
                *(uint32_t*)&Hl[r1*HLD + col] = l1;
            }
        }
    }
    __syncthreads();

    // ---------- Phase 2: out = hidden@W2^T + b2 + H ----------
    float acc2[2][8][4] = {};
    for (int c = 0; c < 8; c++) {
        const int k0 = c * 32;
        #pragma unroll
        for (int i = 0; i < 2; i++) {
            int lin = t + 512 * i;
            int row = lin >> 2, q = lin & 3;
            *(uint4*)&Bsh[row*40 + q*8] = *(const uint4*)(W2h + (size_t)row*DD + k0 + q*8);
            *(uint4*)&Bsl[row*40 + q*8] = *(const uint4*)(W2l + (size_t)row*DD + k0 + q*8);
        }
        __syncthreads();
        #pragma unroll
        for (int kk = 0; kk < 2; kk++) {
            uint32_t ah[2][4], al[2][4];
            #pragma unroll
            for (int mt = 0; mt < 2; mt++) {
                uint32_t offA = (uint32_t)((a_m + mt*16) * HLD + k0 + kk*16 + a_k) * 2;
                LDSM_X4(ah[mt][0], ah[mt][1], ah[mt][2], ah[mt][3], sHh + offA);
                LDSM_X4(al[mt][0], al[mt][1], al[mt][2], al[mt][3], sHl + offA);
            }
            #pragma unroll
            for (int g = 0; g < 4; g++) {
                uint32_t offB = (uint32_t)((b_n + g*16) * 40 + kk*16 + b_k) * 2;
                uint32_t bh[2][2], bl[2][2];
                LDSM_X4(bh[0][0], bh[0][1], bh[1][0], bh[1][1], sBh + offB);
                LDSM_X4(bl[0][0], bl[0][1], bl[1][0], bl[1][1], sBl + offB);
                #pragma unroll
                for (int mt = 0; mt < 2; mt++) {
                    #pragma unroll
                    for (int j = 0; j < 2; j++) {
                        float* d = acc2[mt][g*2 + j];
                        MMA_BF16(d, ah[mt], bh[j]);
                        MMA_BF16(d, ah[mt], bl[j]);
                        MMA_BF16(d, al[mt], bh[j]);
                    }
                }
            }
        }
        __syncthreads();
    }

    // epilogue 2: out = acc2 + b2 + H
    #pragma unroll
    for (int mt = 0; mt < 2; mt++) {
        int mrow0 = m0 + wm + mt*16 + lr;
        int mrow1 = mrow0 + 8;
        #pragma unroll
        for (int nt = 0; nt < 8; nt++) {
            int col = wn + nt*8 + lc;
            float2 bv = *(const float2*)(b2 + col);
            float2 r0 = *(const float2*)(H + (size_t)mrow0*DD + col);
            float2 r1 = *(const float2*)(H + (size_t)mrow1*DD + col);
            float2 o0, o1;
            o0.x = acc2[mt][nt][0] + bv.x + r0.x;
            o0.y = acc2[mt][nt][1] + bv.y + r0.y;
            o1.x = acc2[mt][nt][2] + bv.x + r1.x;
            o1.y = acc2[mt][nt][3] + bv.y + r1.y;
            *(float2*)(out + (size_t)mrow0*DD + col) = o0;
            *(float2*)(out + (size_t)mrow1*DD + col) = o1;
        }
    }
}

// ---------------- launch ----------------
extern "C" void kernel_launch(void* const* d_in, const int* in_sizes, int n_in,
                              void* d_out, int out_size) {
    (void)in_sizes; (void)n_in; (void)out_size;
    const float* H    = (const float*)d_in[0];
    const int*   pid  = (const int*)  d_in[1];
    const float* ln1g = (const float*)d_in[2];
    const float* ln1b = (const float*)d_in[3];
    const float* Wq   = (const float*)d_in[4];
    const float* bq   = (const float*)d_in[5];
    const float* Wk   = (const float*)d_in[6];
    const float* bk   = (const float*)d_in[7];
    const float* Wv   = (const float*)d_in[8];
    const float* bv   = (const float*)d_in[9];
    const float* Wo   = (const float*)d_in[10];
    const float* bo   = (const float*)d_in[11];
    const float* ln2g = (const float*)d_in[12];
    const float* ln2b = (const float*)d_in[13];
    const float* fW1  = (const float*)d_in[14];
    const float* fb1  = (const float*)d_in[15];
    const float* fW2  = (const float*)d_in[16];
    const float* fb2  = (const float*)d_in[17];
    const float* mW1  = (const float*)d_in[18];
    const float* mb1  = (const float*)d_in[19];
    const float* mW2  = (const float*)d_in[20];
    const float* mb2  = (const float*)d_in[21];

    float* out = (float*)d_out;
    float* psu = out + (size_t)SS*NN*DD;

    float *p_x, *p_y, *p_qkv, *p_attn, *p_x2, *p_h, *p_p2, *p_bqkv;
    __nv_bfloat16 *p_wqkvh, *p_wqkvl, *p_woh, *p_wol, *p_f1h, *p_f1l, *p_f2h, *p_f2l;
    __nv_bfloat16 *p_p2h, *p_p2l, *p_w1h, *p_w1l, *p_w2h, *p_w2l;
    cudaGetSymbolAddress((void**)&p_x,     g_x);
    cudaGetSymbolAddress((void**)&p_y,     g_y);
    cudaGetSymbolAddress((void**)&p_qkv,   g_qkv);
    cudaGetSymbolAddress((void**)&p_attn,  g_attn);
    cudaGetSymbolAddress((void**)&p_x2,    g_x2);
    cudaGetSymbolAddress((void**)&p_h,     g_h);
    cudaGetSymbolAddress((void**)&p_p2,    g_p2);
    cudaGetSymbolAddress((void**)&p_bqkv,  g_bqkv);
    cudaGetSymbolAddress((void**)&p_wqkvh, g_wqkvh);
    cudaGetSymbolAddress((void**)&p_wqkvl, g_wqkvl);
    cudaGetSymbolAddress((void**)&p_woh,   g_woh);
    cudaGetSymbolAddress((void**)&p_wol,   g_wol);
    cudaGetSymbolAddress((void**)&p_f1h,   g_f1h);
    cudaGetSymbolAddress((void**)&p_f1l,   g_f1l);
    cudaGetSymbolAddress((void**)&p_f2h,   g_f2h);
    cudaGetSymbolAddress((void**)&p_f2l,   g_f2l);
    cudaGetSymbolAddress((void**)&p_p2h,   g_p2h);
    cudaGetSymbolAddress((void**)&p_p2l,   g_p2l);
    cudaGetSymbolAddress((void**)&p_w1h,   g_w1h);
    cudaGetSymbolAddress((void**)&p_w1l,   g_w1l);
    cudaGetSymbolAddress((void**)&p_w2h,   g_w2h);
    cudaGetSymbolAddress((void**)&p_w2l,   g_w2l);

    static int smem_set = 0;
    if (!smem_set) {
        cudaFuncSetAttribute(k_node, cudaFuncAttributeMaxDynamicSharedMemorySize, NSM_TOTAL);
        smem_set = 1;
    }

    // 1) pooling (count-sort) + weight prep
    k_zero_cnt<<<8, 256>>>();
    k_prep_w<<<3072, 256>>>(Wq, Wk, Wv, bq, bk, bv, Wo, fW1, fW2, mW1, mW2);
    k_count<<<SS*NN/256, 256>>>(pid);
    k_scan<<<1, 256>>>();
    k_scatter<<<SS*NN/256, 256>>>(pid);
    k_patchsum<<<SS*KK, 256>>>(H);

    // 2) patch transformer (all GEMMs on tensor cores)
    k_ln<<<SS*KK, 256>>>(p_x, ln1g, ln1b, p_y);
    k_mma<<<dim3(QKVW/128, (SS*KK)/128), 256>>>(p_y, p_wqkvh, p_wqkvl, p_qkv,
                                                DD, QKVW, 6, p_bqkv, nullptr);
    k_kvsum<<<SS*NHH, 256>>>();
    k_attn<<<SS*KK, 256>>>();
    k_mma<<<dim3(DD/128, (SS*KK)/128), 256>>>(p_attn, p_woh, p_wol, p_x2,
                                              DD, DD, 2, bo, p_x);
    k_ln<<<SS*KK, 256>>>(p_x2, ln2g, ln2b, p_y);
    k_mma<<<dim3(FF/128, (SS*KK)/128), 256>>>(p_y, p_f1h, p_f1l, p_h,
                                              DD, FF, 5, fb1, nullptr);
    k_mma<<<dim3(DD/128, (SS*KK)/128), 256>>>(p_h, p_f2h, p_f2l, psu,
                                              FF, DD, 2, fb2, p_x2);

    // 3) node MLP: p2 precompute, then fused two-GEMM node kernel
    k_mma<<<dim3(DD/128, (SS*KK)/128), 256>>>(psu, p_p2h, p_p2l, p_p2,
                                              DD, DD, 0, mb1, nullptr);
    k_node<<<(SS*NN)/128, 512, NSM_TOTAL>>>(H, p_w1h, p_w1l, p_w2h, p_w2l,
                                            p_p2, pid, mb2, out);
}

// round 8
// speedup vs baseline: 1.1278x; 1.1278x over previous
#include <cuda_runtime.h>
#include <cuda_bf16.h>
#include <math.h>
#include <stdint.h>

// Problem constants
#define SS  4
#define NN  32768
#define DD  256
#define KK  512
#define NHH 4
#define HDD 64
#define FF  1024
#define QKVW 768

// ---------------- scratch (device globals; no runtime allocation) ----------------
__device__ float g_x   [SS*KK*DD];
__device__ int   g_cnt [SS*KK];
__device__ int   g_off [SS*KK];
__device__ int   g_cur [SS*KK];
__device__ int   g_nlist[SS*NN];
__device__ float g_y   [SS*KK*DD];
__device__ float g_qkv [SS*KK*QKVW];
__device__ float g_kv  [SS*NHH*HDD*HDD];
__device__ float g_ksum[SS*NHH*HDD];
__device__ float g_attn[SS*KK*DD];
__device__ float g_x2  [SS*KK*DD];
__device__ float g_h   [SS*KK*FF];
__device__ float g_p2  [SS*KK*DD];
__device__ float g_bqkv[QKVW];
__device__ __nv_bfloat16 g_hidh[SS*NN*DD];  // node hidden, bf16 hi
__device__ __nv_bfloat16 g_hidl[SS*NN*DD];  // node hidden, bf16 lo

// bf16 hi/lo split weights, all [n][k] layout
__device__ __nv_bfloat16 g_wqkvh[QKVW*DD], g_wqkvl[QKVW*DD];
__device__ __nv_bfloat16 g_woh [DD*DD],   g_wol [DD*DD];
__device__ __nv_bfloat16 g_f1h [FF*DD],   g_f1l [FF*DD];
__device__ __nv_bfloat16 g_f2h [DD*FF],   g_f2l [DD*FF];
__device__ __nv_bfloat16 g_p2h [DD*DD],   g_p2l [DD*DD];   // mW1[256:512]
__device__ __nv_bfloat16 g_w1h [DD*DD],   g_w1l [DD*DD];   // mW1[0:256]
__device__ __nv_bfloat16 g_w2h [DD*DD],   g_w2l [DD*DD];   // mW2

// ---------------- small device helpers ----------------
__device__ __forceinline__ float geluf(float x) {
    return 0.5f * x * (1.0f + erff(x * 0.70710678118654752440f));
}
__device__ __forceinline__ float phif(float x) {   // elu(x)+1
    return x > 0.0f ? x + 1.0f : expf(x);
}
__device__ __forceinline__ uint32_t pack_bf2(float a, float b) {
    __nv_bfloat162 t = __floats2bfloat162_rn(a, b);
    return *(uint32_t*)&t;
}
__device__ __forceinline__ float bflo(uint32_t p) {
    __nv_bfloat162 b = *(__nv_bfloat162*)&p; return __bfloat162float(b.x);
}
__device__ __forceinline__ float bfhi(uint32_t p) {
    __nv_bfloat162 b = *(__nv_bfloat162*)&p; return __bfloat162float(b.y);
}
__device__ __forceinline__ uint32_t smem_u32(const void* p) {
    uint32_t a;
    asm("{ .reg .u64 t; cvta.to.shared.u64 t, %1; cvt.u32.u64 %0, t; }" : "=r"(a) : "l"(p));
    return a;
}
#define LDSM_X4(r0, r1, r2, r3, addr) \
    asm volatile("ldmatrix.sync.aligned.m8n8.x4.shared.b16 {%0,%1,%2,%3}, [%4];" \
                 : "=r"(r0), "=r"(r1), "=r"(r2), "=r"(r3) : "r"(addr))
#define MMA_BF16(d, a, b) \
    asm volatile("mma.sync.aligned.m16n8k16.row.col.f32.bf16.bf16.f32 " \
                 "{%0,%1,%2,%3},{%4,%5,%6,%7},{%8,%9},{%0,%1,%2,%3};" \
                 : "+f"((d)[0]), "+f"((d)[1]), "+f"((d)[2]), "+f"((d)[3]) \
                 : "r"((a)[0]), "r"((a)[1]), "r"((a)[2]), "r"((a)[3]), \
                   "r"((b)[0]), "r"((b)[1]))
#define CP_ASYNC16(dst, src) \
    asm volatile("cp.async.cg.shared.global [%0], [%1], 16;" :: "r"(dst), "l"(src))
#define CP_COMMIT() asm volatile("cp.async.commit_group;" ::: "memory")
#define CP_WAIT0()  asm volatile("cp.async.wait_group 0;" ::: "memory")

// dynamic smem layout for pipelined GEMMs (two stages of 4 tiles, 128x32 bf16 pad40)
#define PSM_AH(s) ((s)*10240)
#define PSM_AL(s) (20480 + (s)*10240)
#define PSM_BH(s) (40960 + (s)*10240)
#define PSM_BL(s) (61440 + (s)*10240)
#define PSM_TOTAL 81920

// ---------------- pooling (count-sort, no fp32 atomics) ----------------
__global__ void k_zero_cnt() {
    int i = blockIdx.x * blockDim.x + threadIdx.x;
    if (i < SS*KK) g_cnt[i] = 0;
}

__global__ void k_count(const int* __restrict__ pid) {
    int b = blockIdx.x * blockDim.x + threadIdx.x;
    int s = b >> 15;
    atomicAdd(&g_cnt[s*KK + pid[b]], 1);
}

__global__ void k_scan() {
    __shared__ int part[256];
    int t = threadIdx.x;
    int base = t * 8;
    int loc[8];
    int sum = 0;
    #pragma unroll
    for (int i = 0; i < 8; i++) { loc[i] = sum; sum += g_cnt[base + i]; }
    part[t] = sum;
    __syncthreads();
    #pragma unroll
    for (int off = 1; off < 256; off <<= 1) {
        int v = (t >= off) ? part[t - off] : 0;
        __syncthreads();
        part[t] += v;
        __syncthreads();
    }
    int prev = (t > 0) ? part[t - 1] : 0;
    #pragma unroll
    for (int i = 0; i < 8; i++) {
        g_off[base + i] = prev + loc[i];
        g_cur[base + i] = prev + loc[i];
    }
}

__global__ void k_scatter(const int* __restrict__ pid) {
    int b = blockIdx.x * blockDim.x + threadIdx.x;
    int s = b >> 15;
    int pos = atomicAdd(&g_cur[s*KK + pid[b]], 1);
    g_nlist[pos] = b;
}

__global__ __launch_bounds__(256) void k_patchsum(const float* __restrict__ H) {
    int r = blockIdx.x;
    int d = threadIdx.x;
    int cnt = g_cnt[r];
    int off = g_off[r];
    float a0 = 0.f, a1 = 0.f, a2 = 0.f, a3 = 0.f;
    int i = 0;
    for (; i + 4 <= cnt; i += 4) {
        int n0 = g_nlist[off+i],   n1 = g_nlist[off+i+1];
        int n2 = g_nlist[off+i+2], n3 = g_nlist[off+i+3];
        a0 += __ldg(&H[(size_t)n0*DD + d]);
        a1 += __ldg(&H[(size_t)n1*DD + d]);
        a2 += __ldg(&H[(size_t)n2*DD + d]);
        a3 += __ldg(&H[(size_t)n3*DD + d]);
    }
    for (; i < cnt; i++) a0 += __ldg(&H[(size_t)g_nlist[off+i]*DD + d]);
    float sum = (a0 + a1) + (a2 + a3);
    float inv = (cnt > 0) ? (1.0f / (float)cnt) : 0.0f;
    g_x[(size_t)r*DD + d] = sum * inv;
}

// ---------------- weight prep ----------------
__global__ void k_prep_w(const float* __restrict__ Wq, const float* __restrict__ Wk,
                         const float* __restrict__ Wv, const float* __restrict__ bq,
                         const float* __restrict__ bk, const float* __restrict__ bv,
                         const float* __restrict__ Wo, const float* __restrict__ fW1,
                         const float* __restrict__ fW2, const float* __restrict__ mW1,
                         const float* __restrict__ mW2) {
    int r = blockIdx.x, t = threadIdx.x;
    if (r < 768) {
        int n = r;
        float v = (n < 256) ? Wq[t*DD + n] : (n < 512) ? Wk[t*DD + (n-256)] : Wv[t*DD + (n-512)];
        __nv_bfloat16 h = __float2bfloat16(v);
        g_wqkvh[n*DD + t] = h;
        g_wqkvl[n*DD + t] = __float2bfloat16(v - __bfloat162float(h));
        if (t == 0) g_bqkv[n] = (n < 256) ? bq[n] : (n < 512) ? bk[n-256] : bv[n-512];
    } else if (r < 1024) {
        int n = r - 768;
        float v = Wo[t*DD + n];
        __nv_bfloat16 h = __float2bfloat16(v);
        g_woh[n*DD + t] = h;
        g_wol[n*DD + t] = __float2bfloat16(v - __bfloat162float(h));
    } else if (r < 2048) {
        int n = r - 1024;
        float v = fW1[t*FF + n];
        __nv_bfloat16 h = __float2bfloat16(v);
        g_f1h[n*DD + t] = h;
        g_f1l[n*DD + t] = __float2bfloat16(v - __bfloat162float(h));
    } else if (r < 2304) {
        int n = r - 2048;
        #pragma unroll
        for (int kk = 0; kk < 4; kk++) {
            int k = t + kk*256;
            float v = fW2[k*DD + n];
            __nv_bfloat16 h = __float2bfloat16(v);
            g_f2h[n*FF + k] = h;
            g_f2l[n*FF + k] = __float2bfloat16(v - __bfloat162float(h));
        }
    } else if (r < 2560) {
        int n = r - 2304;
        float v = mW1[(256 + t)*DD + n];
        __nv_bfloat16 h = __float2bfloat16(v);
        g_p2h[n*DD + t] = h;
        g_p2l[n*DD + t] = __float2bfloat16(v - __bfloat162float(h));
    } else if (r < 2816) {
        int n = r - 2560;
        float v = mW1[t*DD + n];
        __nv_bfloat16 h = __float2bfloat16(v);
        g_w1h[n*DD + t] = h;
        g_w1l[n*DD + t] = __float2bfloat16(v - __bfloat162float(h));
    } else {
        int n = r - 2816;
        float v = mW2[t*DD + n];
        __nv_bfloat16 h = __float2bfloat16(v);
        g_w2h[n*DD + t] = h;
        g_w2l[n*DD + t] = __float2bfloat16(v - __bfloat162float(h));
    }
}

// ---------------- layer norm ----------------
__global__ void k_ln(const float* __restrict__ in, const float* __restrict__ gw,
                     const float* __restrict__ bw, float* __restrict__ out) {
    int r = blockIdx.x, d = threadIdx.x;
    float v = in[(size_t)r*DD + d];
    __shared__ float s1[8], s2[8];
    __shared__ float smu, sri;
    float a = v, b = v * v;
    #pragma unroll
    for (int o = 16; o > 0; o >>= 1) {
        a += __shfl_down_sync(0xffffffffu, a, o);
        b += __shfl_down_sync(0xffffffffu, b, o);
    }
    if ((d & 31) == 0) { s1[d >> 5] = a; s2[d >> 5] = b; }
    __syncthreads();
    if (d == 0) {
        float sa = 0.f, sb = 0.f;
        #pragma unroll
        for (int i = 0; i < 8; i++) { sa += s1[i]; sb += s2[i]; }
        float m   = sa * (1.0f / DD);
        float var = sb * (1.0f / DD) - m * m;
        smu = m; sri = rsqrtf(var + 1e-5f);
    }
    __syncthreads();
    out[(size_t)r*DD + d] = (v - smu) * sri * gw[d] + bw[d];
}

__global__ __launch_bounds__(256) void k_kvsum() {
    int b = blockIdx.x;
    int s = b >> 2, h = b & 3;
    int t = threadIdx.x, tx = t & 15, ty = t >> 4;
    __shared__ float ks[8][64], vs[8][64];
    float acc[4][4] = {};
    float ksl = 0.0f;
    const float* kp = g_qkv + (size_t)s*KK*QKVW + 256 + h*HDD;
    const float* vp = g_qkv + (size_t)s*KK*QKVW + 512 + h*HDD;

    for (int k0 = 0; k0 < KK; k0 += 8) {
        #pragma unroll
        for (int u = 0; u < 2; u++) {
            int idx = t + u*256; int i = idx >> 6, d = idx & 63;
            ks[i][d] = kp[(size_t)(k0 + i)*QKVW + d];
            vs[i][d] = vp[(size_t)(k0 + i)*QKVW + d];
        }
        __syncthreads();
        if (t < 64) {
            #pragma unroll
            for (int i = 0; i < 8; i++) ksl += ks[i][t];
        }
        #pragma unroll
        for (int i = 0; i < 8; i++) {
            float kd[4], ve[4];
            #pragma unroll
            for (int j = 0; j < 4; j++) { kd[j] = ks[i][ty*4+j]; ve[j] = vs[i][tx*4+j]; }
            #pragma unroll
            for (int a = 0; a < 4; a++)
                #pragma unroll
                for (int c = 0; c < 4; c++)
                    acc[a][c] += kd[a] * ve[c];
        }
        __syncthreads();
    }
    if (t < 64) g_ksum[(size_t)b*64 + t] = ksl;
    #pragma unroll
    for (int a = 0; a < 4; a++)
        #pragma unroll
        for (int c = 0; c < 4; c++)
            g_kv[((size_t)b*64 + ty*4 + a)*64 + tx*4 + c] = acc[a][c];
}

__global__ void k_attn() {
    int r = blockIdx.x;
    int s = r / KK;
    int t = threadIdx.x;
    __shared__ float qs[256];
    qs[t] = g_qkv[(size_t)r*QKVW + t];
    __syncthreads();
    int h = t >> 6, e = t & 63;
    const float* kvp = g_kv   + (size_t)(s*NHH + h)*HDD*HDD;
    const float* ksp = g_ksum + (size_t)(s*NHH + h)*HDD;
    float num = 0.f, den = 0.f;
    #pragma unroll 8
    for (int d = 0; d < 64; d++) {
        float q = qs[h*64 + d];
        num += q * kvp[d*64 + e];
        den += q * ksp[d];
    }
    g_attn[(size_t)r*DD + t] = num / (den + 1e-6f);
}

// ---- Pipelined tensor-core GEMM (fp32 A): C = epi(A[M,Kd] @ Bt^T) ----
// Double-buffered smem; B via cp.async, A reg-prefetch + convert.
// modes: 0: +bias; 2: +bias+res; 5: gelu(+bias); 6: qkv epilogue;
//        7: node GEMM1 -> gelu(acc + p2[pid gather]) stored to g_hidh/g_hidl (bf16 split)
__global__ __launch_bounds__(256, 2) void k_mma_p(
    const float* __restrict__ A,
    const __nv_bfloat16* __restrict__ Bh,
    const __nv_bfloat16* __restrict__ Bl,
    float* __restrict__ C, int Kd, int Cld, int mode,
    const float* __restrict__ bias, const float* __restrict__ res,
    const float* __restrict__ p2, const int* __restrict__ pid)
{
    extern __shared__ char sm[];
    const uint32_t sb = smem_u32(sm);

    const int t = threadIdx.x, lane = t & 31, wid = t >> 5;
    const int n0 = blockIdx.x * 128, m0 = blockIdx.y * 128;
    const int wm = (wid & 3) * 32;
    const int wn = (wid >> 2) * 64;

    const int a_m = wm + (lane & 15);
    const int a_k = (lane >> 4) << 3;
    const int b_n = wn + ((lane >> 4) << 3) + (lane & 7);
    const int b_k = ((lane >> 3) & 1) << 3;

    const int ar = t >> 3, aq = t & 7;          // A load: row, quad (4 floats)
    const int br = t >> 2, bq = t & 3;          // B cp.async: row pair base

    float acc[2][8][4] = {};
    const int nch = Kd >> 5;
    float4 apre[4];

    // --- helpers (macros via lambdas) ---
    auto loadA = [&](int c) {
        const float* Ab = A + (size_t)m0*Kd + c*32;
        #pragma unroll
        for (int i = 0; i < 4; i++)
            apre[i] = *(const float4*)(Ab + (size_t)(ar + 32*i)*Kd + aq*4);
    };
    auto storeA = [&](int stg) {
        #pragma unroll
        for (int i = 0; i < 4; i++) {
            float4 f = apre[i];
            uint32_t h01 = pack_bf2(f.x, f.y);
            uint32_t h23 = pack_bf2(f.z, f.w);
            uint32_t l01 = pack_bf2(f.x - bflo(h01), f.y - bfhi(h01));
            uint32_t l23 = pack_bf2(f.z - bflo(h23), f.w - bfhi(h23));
            uint32_t eo = ((ar + 32*i)*40 + aq*4) * 2;
            *(uint2*)(sm + PSM_AH(stg) + eo) = make_uint2(h01, h23);
            *(uint2*)(sm + PSM_AL(stg) + eo) = make_uint2(l01, l23);
        }
    };
    auto loadB = [&](int c, int stg) {
        const int k0 = c * 32;
        #pragma unroll
        for (int i = 0; i < 2; i++) {
            int row = br + 64*i;
            uint32_t eo = (row*40 + bq*8) * 2;
            CP_ASYNC16(sb + PSM_BH(stg) + eo,
                       (const void*)(Bh + (size_t)(n0 + row)*Kd + k0 + bq*8));
            CP_ASYNC16(sb + PSM_BL(stg) + eo,
                       (const void*)(Bl + (size_t)(n0 + row)*Kd + k0 + bq*8));
        }
        CP_COMMIT();
    };

    // --- prologue ---
    loadA(0);
    loadB(0, 0);
    storeA(0);
    CP_WAIT0();
    __syncthreads();

    for (int c = 0; c < nch; c++) {
        const int cur = c & 1, nxt = cur ^ 1;
        const bool more = (c + 1 < nch);
        if (more) { loadA(c + 1); loadB(c + 1, nxt); }

        #pragma unroll
        for (int kk = 0; kk < 2; kk++) {
            uint32_t ah[2][4], al[2][4];
            #pragma unroll
            for (int mt = 0; mt < 2; mt++) {
                uint32_t eo = (uint32_t)((a_m + mt*16) * 40 + kk*16 + a_k) * 2;
                LDSM_X4(ah[mt][0], ah[mt][1], ah[mt][2], ah[mt][3], sb + PSM_AH(cur) + eo);
                LDSM_X4(al[mt][0], al[mt][1], al[mt][2], al[mt][3], sb + PSM_AL(cur) + eo);
            }
            #pragma unroll
            for (int g = 0; g < 4; g++) {
                uint32_t eo = (uint32_t)((b_n + g*16) * 40 + kk*16 + b_k) * 2;
                uint32_t bh[2][2], bl[2][2];
                LDSM_X4(bh[0][0], bh[0][1], bh[1][0], bh[1][1], sb + PSM_BH(cur) + eo);
                LDSM_X4(bl[0][0], bl[0][1], bl[1][0], bl[1][1], sb + PSM_BL(cur) + eo);
                #pragma unroll
                for (int mt = 0; mt < 2; mt++) {
                    #pragma unroll
                    for (int j = 0; j < 2; j++) {
                        float* d = acc[mt][g*2 + j];
                        MMA_BF16(d, ah[mt], bh[j]);
                        MMA_BF16(d, ah[mt], bl[j]);
                        MMA_BF16(d, al[mt], bh[j]);
                    }
                }
            }
        }
        if (more) { storeA(nxt); CP_WAIT0(); }
        __syncthreads();
    }

    const int lr = lane >> 2;
    const int lc = (lane & 3) * 2;
    #pragma unroll
    for (int mt = 0; mt < 2; mt++) {
        int mrow0 = m0 + wm + mt*16 + lr;
        int mrow1 = mrow0 + 8;
        if (mode == 7) {
            int s0 = mrow0 >> 15, s1 = mrow1 >> 15;
            const float* p2r0 = p2 + ((size_t)(s0*KK + pid[mrow0]))*DD;
            const float* p2r1 = p2 + ((size_t)(s1*KK + pid[mrow1]))*DD;
            #pragma unroll
            for (int nt = 0; nt < 8; nt++) {
                int col = n0 + wn + nt*8 + lc;
                float v00 = geluf(acc[mt][nt][0] + p2r0[col]);
                float v01 = geluf(acc[mt][nt][1] + p2r0[col+1]);
                float v10 = geluf(acc[mt][nt][2] + p2r1[col]);
                float v11 = geluf(acc[mt][nt][3] + p2r1[col+1]);
                uint32_t h0 = pack_bf2(v00, v01);
                uint32_t l0 = pack_bf2(v00 - bflo(h0), v01 - bfhi(h0));
                uint32_t h1 = pack_bf2(v10, v11);
                uint32_t l1 = pack_bf2(v10 - bflo(h1), v11 - bfhi(h1));
                *(uint32_t*)&g_hidh[(size_t)mrow0*DD + col] = h0;
                *(uint32_t*)&g_hidl[(size_t)mrow0*DD + col] = l0;
                *(uint32_t*)&g_hidh[(size_t)mrow1*DD + col] = h1;
                *(uint32_t*)&g_hidl[(size_t)mrow1*DD + col] = l1;
            }
        } else if (mode == 2) {
            #pragma unroll
            for (int nt = 0; nt < 8; nt++) {
                int col = n0 + wn + nt*8 + lc;
                float2 bv = *(const float2*)(bias + col);
                float2 r0 = *(const float2*)(res + (size_t)mrow0*Cld + col);
                float2 r1 = *(const float2*)(res + (size_t)mrow1*Cld + col);
                float2 o0, o1;
                o0.x = acc[mt][nt][0] + bv.x + r0.x;
                o0.y = acc[mt][nt][1] + bv.y + r0.y;
                o1.x = acc[mt][nt][2] + bv.x + r1.x;
                o1.y = acc[mt][nt][3] + bv.y + r1.y;
                *(float2*)(C + (size_t)mrow0*Cld + col) = o0;
                *(float2*)(C + (size_t)mrow1*Cld + col) = o1;
            }
        } else if (mode == 5) {
            #pragma unroll
            for (int nt = 0; nt < 8; nt++) {
                int col = n0 + wn + nt*8 + lc;
                float2 bv = *(const float2*)(bias + col);
                float2 o0, o1;
                o0.x = geluf(acc[mt][nt][0] + bv.x);
                o0.y = geluf(acc[mt][nt][1] + bv.y);
                o1.x = geluf(acc[mt][nt][2] + bv.x);
                o1.y = geluf(acc[mt][nt][3] + bv.y);
                *(float2*)(C + (size_t)mrow0*Cld + col) = o0;
                *(float2*)(C + (size_t)mrow1*Cld + col) = o1;
            }
        } else if (mode == 6) {
            float mk0 = (g_cnt[mrow0] > 0) ? 1.0f : 0.0f;
            float mk1 = (g_cnt[mrow1] > 0) ? 1.0f : 0.0f;
            #pragma unroll
            for (int nt = 0; nt < 8; nt++) {
                int col = n0 + wn + nt*8 + lc;
                float2 bv = *(const float2*)(bias + col);
                float v00 = acc[mt][nt][0] + bv.x, v01 = acc[mt][nt][1] + bv.y;
                float v10 = acc[mt][nt][2] + bv.x, v11 = acc[mt][nt][3] + bv.y;
                float2 o0, o1;
                if (col < 256) {
                    o0.x = phif(v00); o0.y = phif(v01);
                    o1.x = phif(v10); o1.y = phif(v11);
                } else if (col < 512) {
                    o0.x = phif(v00) * mk0; o0.y = phif(v01) * mk0;
                    o1.x = phif(v10) * mk1; o1.y = phif(v11) * mk1;
                } else {
                    o0.x = v00 * mk0; o0.y = v01 * mk0;
                    o1.x = v10 * mk1; o1.y = v11 * mk1;
                }
                *(float2*)(C + (size_t)mrow0*Cld + col) = o0;
                *(float2*)(C + (size_t)mrow1*Cld + col) = o1;
            }
        } else { // mode 0
            #pragma unroll
            for (int nt = 0; nt < 8; nt++) {
                int col = n0 + wn + nt*8 + lc;
                float2 bv = *(const float2*)(bias + col);
                float2 o0, o1;
                o0.x = acc[mt][nt][0] + bv.x;
                o0.y = acc[mt][nt][1] + bv.y;
                o1.x = acc[mt][nt][2] + bv.x;
                o1.y = acc[mt][nt][3] + bv.y;
                *(float2*)(C + (size_t)mrow0*Cld + col) = o0;
                *(float2*)(C + (size_t)mrow1*Cld + col) = o1;
            }
        }
    }
}

// ---- Node GEMM2: out = hid@W2^T + b2 + H. A (g_hidh/g_hidl) via cp.async too. ----
__global__ __launch_bounds__(256, 2) void k_mma_n2(
    const float* __restrict__ H, const float* __restrict__ b2,
    float* __restrict__ out)
{
    extern __shared__ char sm[];
    const uint32_t sb = smem_u32(sm);

    const int t = threadIdx.x, lane = t & 31, wid = t >> 5;
    const int n0 = blockIdx.x * 128, m0 = blockIdx.y * 128;
    const int wm = (wid & 3) * 32;
    const int wn = (wid >> 2) * 64;

    const int a_m = wm + (lane & 15);
    const int a_k = (lane >> 4) << 3;
    const int b_n = wn + ((lane >> 4) << 3) + (lane & 7);
    const int b_k = ((lane >> 3) & 1) << 3;
    const int br = t >> 2, bq = t & 3;     // 64 rows x 4 quads per pass

    float acc[2][8][4] = {};

    auto loadAB = [&](int c, int stg) {
        const int k0 = c * 32;
        #pragma unroll
        for (int i = 0; i < 2; i++) {
            int row = br + 64*i;
            uint32_t eo = (row*40 + bq*8) * 2;
            CP_ASYNC16(sb + PSM_AH(stg) + eo,
                       (const void*)(g_hidh + (size_t)(m0 + row)*DD + k0 + bq*8));
            CP_ASYNC16(sb + PSM_AL(stg) + eo,
                       (const void*)(g_hidl + (size_t)(m0 + row)*DD + k0 + bq*8));
            CP_ASYNC16(sb + PSM_BH(stg) + eo,
                       (const void*)(g_w2h + (size_t)(n0 + row)*DD + k0 + bq*8));
            CP_ASYNC16(sb + PSM_BL(stg) + eo,
                       (const void*)(g_w2l + (size_t)(n0 + row)*DD + k0 + bq*8));
        }
        CP_COMMIT();
    };

    loadAB(0, 0);
    CP_WAIT0();
    __syncthreads();

    for (int c = 0; c < 8; c++) {
        const int cur = c & 1, nxt = cur ^ 1;
        const bool more = (c + 1 < 8);
        if (more) loadAB(c + 1, nxt);

        #pragma unroll
        for (int kk = 0; kk < 2; kk++) {
            uint32_t ah[2][4], al[2][4];
            #pragma unroll
            for (int mt = 0; mt < 2; mt++) {
                uint32_t eo = (uint32_t)((a_m + mt*16) * 40 + kk*16 + a_k) * 2;
                LDSM_X4(ah[mt][0], ah[mt][1], ah[mt][2], ah[mt][3], sb + PSM_AH(cur) + eo);
                LDSM_X4(al[mt][0], al[mt][1], al[mt][2], al[mt][3], sb + PSM_AL(cur) + eo);
            }
            #pragma unroll
            for (int g = 0; g < 4; g++) {
                uint32_t eo = (uint32_t)((b_n + g*16) * 40 + kk*16 + b_k) * 2;
                uint32_t bh[2][2], bl[2][2];
                LDSM_X4(bh[0][0], bh[0][1], bh[1][0], bh[1][1], sb + PSM_BH(cur) + eo);
                LDSM_X4(bl[0][0], bl[0][1], bl[1][0], bl[1][1], sb + PSM_BL(cur) + eo);
                #pragma unroll
                for (int mt = 0; mt < 2; mt++) {
                    #pragma unroll
                    for (int j = 0; j < 2; j++) {
                        float* d = acc[mt][g*2 + j];
                        MMA_BF16(d, ah[mt], bh[j]);
                        MMA_BF16(d, ah[mt], bl[j]);
                        MMA_BF16(d, al[mt], bh[j]);
                    }
                }
            }
        }
        if (more) CP_WAIT0();
        __syncthreads();
    }

    const int lr = lane >> 2;
    const int lc = (lane & 3) * 2;
    #pragma unroll
    for (int mt = 0; mt < 2; mt++) {
        int mrow0 = m0 + wm + mt*16 + lr;
        int mrow1 = mrow0 + 8;
        #pragma unroll
        for (int nt = 0; nt < 8; nt++) {
            int col = n0 + wn + nt*8 + lc;
            float2 bv = *(const float2*)(b2 + col);
            float2 r0 = *(const float2*)(H + (size_t)mrow0*DD + col);
            float2 r1 = *(const float2*)(H + (size_t)mrow1*DD + col);
            float2 o0, o1;
            o0.x = acc[mt][nt][0] + bv.x + r0.x;
            o0.y = acc[mt][nt][1] + bv.y + r0.y;
            o1.x = acc[mt][nt][2] + bv.x + r1.x;
            o1.y = acc[mt][nt][3] + bv.y + r1.y;
            *(float2*)(out + (size_t)mrow0*DD + col) = o0;
            *(float2*)(out + (size_t)mrow1*DD + col) = o1;
        }
    }
}

// ---------------- launch ----------------
extern "C" void kernel_launch(void* const* d_in, const int* in_sizes, int n_in,
                              void* d_out, int out_size) {
    (void)in_sizes; (void)n_in; (void)out_size;
    const float* H    = (const float*)d_in[0];
    const int*   pid  = (const int*)  d_in[1];
    const float* ln1g = (const float*)d_in[2];
    const float* ln1b = (const float*)d_in[3];
    const float* Wq   = (const float*)d_in[4];
    const float* bq   = (const float*)d_in[5];
    const float* Wk   = (const float*)d_in[6];
    const float* bk   = (const float*)d_in[7];
    const float* Wv   = (const float*)d_in[8];
    const float* bv   = (const float*)d_in[9];
    const float* Wo   = (const float*)d_in[10];
    const float* bo   = (const float*)d_in[11];
    const float* ln2g = (const float*)d_in[12];
    const float* ln2b = (const float*)d_in[13];
    const float* fW1  = (const float*)d_in[14];
    const float* fb1  = (const float*)d_in[15];
    const float* fW2  = (const float*)d_in[16];
    const float* fb2  = (const float*)d_in[17];
    const float* mW1  = (const float*)d_in[18];
    const float* mb1  = (const float*)d_in[19];
    const float* mW2  = (const float*)d_in[20];
    const float* mb2  = (const float*)d_in[21];

    float* out = (float*)d_out;
    float* psu = out + (size_t)SS*NN*DD;

    float *p_x, *p_y, *p_qkv, *p_attn, *p_x2, *p_h, *p_p2, *p_bqkv;
    __nv_bfloat16 *p_wqkvh, *p_wqkvl, *p_woh, *p_wol, *p_f1h, *p_f1l, *p_f2h, *p_f2l;
    __nv_bfloat16 *p_p2h, *p_p2l, *p_w1h, *p_w1l;
    cudaGetSymbolAddress((void**)&p_x,     g_x);
    cudaGetSymbolAddress((void**)&p_y,     g_y);
    cudaGetSymbolAddress((void**)&p_qkv,   g_qkv);
    cudaGetSymbolAddress((void**)&p_attn,  g_attn);
    cudaGetSymbolAddress((void**)&p_x2,    g_x2);
    cudaGetSymbolAddress((void**)&p_h,     g_h);
    cudaGetSymbolAddress((void**)&p_p2,    g_p2);
    cudaGetSymbolAddress((void**)&p_bqkv,  g_bqkv);
    cudaGetSymbolAddress((void**)&p_wqkvh, g_wqkvh);
    cudaGetSymbolAddress((void**)&p_wqkvl, g_wqkvl);
    cudaGetSymbolAddress((void**)&p_woh,   g_woh);
    cudaGetSymbolAddress((void**)&p_wol,   g_wol);
    cudaGetSymbolAddress((void**)&p_f1h,   g_f1h);
    cudaGetSymbolAddress((void**)&p_f1l,   g_f1l);
    cudaGetSymbolAddress((void**)&p_f2h,   g_f2h);
    cudaGetSymbolAddress((void**)&p_f2l,   g_f2l);
    cudaGetSymbolAddress((void**)&p_p2h,   g_p2h);
    cudaGetSymbolAddress((void**)&p_p2l,   g_p2l);
    cudaGetSymbolAddress((void**)&p_w1h,   g_w1h);
    cudaGetSymbolAddress((void**)&p_w1l,   g_w1l);

    static int smem_set = 0;
    if (!smem_set) {
        cudaFuncSetAttribute(k_mma_p,  cudaFuncAttributeMaxDynamicSharedMemorySize, PSM_TOTAL);
        cudaFuncSetAttribute(k_mma_n2, cudaFuncAttributeMaxDynamicSharedMemorySize, PSM_TOTAL);
        smem_set = 1;
    }

    // 1) pooling (count-sort) + weight prep
    k_zero_cnt<<<8, 256>>>();
    k_prep_w<<<3072, 256>>>(Wq, Wk, Wv, bq, bk, bv, Wo, fW1, fW2, mW1, mW2);
    k_count<<<SS*NN/256, 256>>>(pid);
    k_scan<<<1, 256>>>();
    k_scatter<<<SS*NN/256, 256>>>(pid);
    k_patchsum<<<SS*KK, 256>>>(H);

    // 2) patch transformer (pipelined tensor-core GEMMs)
    k_ln<<<SS*KK, 256>>>(p_x, ln1g, ln1b, p_y);
    k_mma_p<<<dim3(QKVW/128, (SS*KK)/128), 256, PSM_TOTAL>>>(
        p_y, p_wqkvh, p_wqkvl, p_qkv, DD, QKVW, 6, p_bqkv, nullptr, nullptr, nullptr);
    k_kvsum<<<SS*NHH, 256>>>();
    k_attn<<<SS*KK, 256>>>();
    k_mma_p<<<dim3(DD/128, (SS*KK)/128), 256, PSM_TOTAL>>>(
        p_attn, p_woh, p_wol, p_x2, DD, DD, 2, bo, p_x, nullptr, nullptr);
    k_ln<<<SS*KK, 256>>>(p_x2, ln2g, ln2b, p_y);
    k_mma_p<<<dim3(FF/128, (SS*KK)/128), 256, PSM_TOTAL>>>(
        p_y, p_f1h, p_f1l, p_h, DD, FF, 5, fb1, nullptr, nullptr, nullptr);
    k_mma_p<<<dim3(DD/128, (SS*KK)/128), 256, PSM_TOTAL>>>(
        p_h, p_f2h, p_f2l, psu, FF, DD, 2, fb2, p_x2, nullptr, nullptr);

    // 3) node MLP: p2 precompute, GEMM1 (writes bf16 hidden), GEMM2
    k_mma_p<<<dim3(DD/128, (SS*KK)/128), 256, PSM_TOTAL>>>(
        psu, p_p2h, p_p2l, p_p2, DD, DD, 0, mb1, nullptr, nullptr, nullptr);
    dim3 gb(DD/128, (SS*NN)/128);
    k_mma_p<<<gb, 256, PSM_TOTAL>>>(
        H, p_w1h, p_w1l, nullptr, DD, DD, 7, nullptr, nullptr, p_p2, pid);
    k_mma_n2<<<gb, 256, PSM_TOTAL>>>(H, mb2, out);
}

// round 9
// speedup vs baseline: 1.3327x; 1.1817x over previous
#include <cuda_runtime.h>
#include <cuda_bf16.h>
#include <cuda_fp16.h>
#include <math.h>
#include <stdint.h>

// Problem constants
#define SS  4
#define NN  32768
#define DD  256
#define KK  512
#define NHH 4
#define HDD 64
#define FF  1024
#define QKVW 768

// ---------------- scratch (device globals; no runtime allocation) ----------------
__device__ float g_x   [SS*KK*DD];
__device__ int   g_cnt [SS*KK];
__device__ int   g_off [SS*KK];
__device__ int   g_cur [SS*KK];
__device__ int   g_nlist[SS*NN];
__device__ float g_y   [SS*KK*DD];
__device__ float g_qkv [SS*KK*QKVW];
__device__ float g_kv  [SS*NHH*HDD*HDD];
__device__ float g_ksum[SS*NHH*HDD];
__device__ float g_attn[SS*KK*DD];
__device__ float g_x2  [SS*KK*DD];
__device__ float g_h   [SS*KK*FF];
__device__ float g_p2  [SS*KK*DD];
__device__ float g_bqkv[QKVW];
__device__ __half g_hidf[SS*NN*DD];        // node hidden, fp16

// bf16 hi/lo split weights (patch side), all [n][k] layout
__device__ __nv_bfloat16 g_wqkvh[QKVW*DD], g_wqkvl[QKVW*DD];
__device__ __nv_bfloat16 g_woh [DD*DD],   g_wol [DD*DD];
__device__ __nv_bfloat16 g_f1h [FF*DD],   g_f1l [FF*DD];
__device__ __nv_bfloat16 g_f2h [DD*FF],   g_f2l [DD*FF];
__device__ __nv_bfloat16 g_p2h [DD*DD],   g_p2l [DD*DD];   // mW1[256:512]
// fp16 node weights, [n][k]
__device__ __half g_w1f [DD*DD];           // mW1[0:256] rounded to fp16
__device__ __half g_w2fh[DD*DD], g_w2fl[DD*DD];  // mW2 fp16 hi/lo

// ---------------- small device helpers ----------------
__device__ __forceinline__ float geluf(float x) {
    return 0.5f * x * (1.0f + erff(x * 0.70710678118654752440f));
}
__device__ __forceinline__ float phif(float x) {   // elu(x)+1
    return x > 0.0f ? x + 1.0f : expf(x);
}
__device__ __forceinline__ uint32_t pack_bf2(float a, float b) {
    __nv_bfloat162 t = __floats2bfloat162_rn(a, b);
    return *(uint32_t*)&t;
}
__device__ __forceinline__ float bflo(uint32_t p) {
    __nv_bfloat162 b = *(__nv_bfloat162*)&p; return __bfloat162float(b.x);
}
__device__ __forceinline__ float bfhi(uint32_t p) {
    __nv_bfloat162 b = *(__nv_bfloat162*)&p; return __bfloat162float(b.y);
}
__device__ __forceinline__ uint32_t pack_hf2(float a, float b) {
    __half2 t = __floats2half2_rn(a, b);
    return *(uint32_t*)&t;
}
__device__ __forceinline__ float hflo(uint32_t p) {
    __half2 h = *(__half2*)&p; return __half2float(h.x);
}
__device__ __forceinline__ float hfhi(uint32_t p) {
    __half2 h = *(__half2*)&p; return __half2float(h.y);
}
__device__ __forceinline__ uint32_t smem_u32(const void* p) {
    uint32_t a;
    asm("{ .reg .u64 t; cvta.to.shared.u64 t, %1; cvt.u32.u64 %0, t; }" : "=r"(a) : "l"(p));
    return a;
}
#define LDSM_X4(r0, r1, r2, r3, addr) \
    asm volatile("ldmatrix.sync.aligned.m8n8.x4.shared.b16 {%0,%1,%2,%3}, [%4];" \
                 : "=r"(r0), "=r"(r1), "=r"(r2), "=r"(r3) : "r"(addr))
#define MMA_BF16(d, a, b) \
    asm volatile("mma.sync.aligned.m16n8k16.row.col.f32.bf16.bf16.f32 " \
                 "{%0,%1,%2,%3},{%4,%5,%6,%7},{%8,%9},{%0,%1,%2,%3};" \
                 : "+f"((d)[0]), "+f"((d)[1]), "+f"((d)[2]), "+f"((d)[3]) \
                 : "r"((a)[0]), "r"((a)[1]), "r"((a)[2]), "r"((a)[3]), \
                   "r"((b)[0]), "r"((b)[1]))
#define MMA_F16(d, a, b) \
    asm volatile("mma.sync.aligned.m16n8k16.row.col.f32.f16.f16.f32 " \
                 "{%0,%1,%2,%3},{%4,%5,%6,%7},{%8,%9},{%0,%1,%2,%3};" \
                 : "+f"((d)[0]), "+f"((d)[1]), "+f"((d)[2]), "+f"((d)[3]) \
                 : "r"((a)[0]), "r"((a)[1]), "r"((a)[2]), "r"((a)[3]), \
                   "r"((b)[0]), "r"((b)[1]))
#define CP_ASYNC16(dst, src) \
    asm volatile("cp.async.cg.shared.global [%0], [%1], 16;" :: "r"(dst), "l"(src))
#define CP_COMMIT() asm volatile("cp.async.commit_group;" ::: "memory")
#define CP_WAIT0()  asm volatile("cp.async.wait_group 0;" ::: "memory")

// dynamic smem layout for pipelined patch GEMMs (two stages of 4 tiles, 128x32 b16 pad40)
#define PSM_AH(s) ((s)*10240)
#define PSM_AL(s) (20480 + (s)*10240)
#define PSM_BH(s) (40960 + (s)*10240)
#define PSM_BL(s) (61440 + (s)*10240)
#define PSM_TOTAL 81920

// node kernels: 3 tile families x 2 stages
#define NS_T0(s) ((s)*10240)
#define NS_T1(s) (20480 + (s)*10240)
#define NS_T2(s) (40960 + (s)*10240)
#define NS_TOTAL 61440

// ---------------- pooling (count-sort, no fp32 atomics) ----------------
__global__ void k_count(const int* __restrict__ pid) {
    int b = blockIdx.x * blockDim.x + threadIdx.x;
    int s = b >> 15;
    atomicAdd(&g_cnt[s*KK + pid[b]], 1);
}

__global__ void k_scan() {
    __shared__ int part[256];
    int t = threadIdx.x;
    int base = t * 8;
    int loc[8];
    int sum = 0;
    #pragma unroll
    for (int i = 0; i < 8; i++) { loc[i] = sum; sum += g_cnt[base + i]; }
    part[t] = sum;
    __syncthreads();
    #pragma unroll
    for (int off = 1; off < 256; off <<= 1) {
        int v = (t >= off) ? part[t - off] : 0;
        __syncthreads();
        part[t] += v;
        __syncthreads();
    }
    int prev = (t > 0) ? part[t - 1] : 0;
    #pragma unroll
    for (int i = 0; i < 8; i++) {
        g_off[base + i] = prev + loc[i];
        g_cur[base + i] = prev + loc[i];
    }
}

__global__ void k_scatter(const int* __restrict__ pid) {
    int b = blockIdx.x * blockDim.x + threadIdx.x;
    int s = b >> 15;
    int pos = atomicAdd(&g_cur[s*KK + pid[b]], 1);
    g_nlist[pos] = b;
}

__global__ __launch_bounds__(256) void k_patchsum(const float* __restrict__ H) {
    int r = blockIdx.x;
    int d = threadIdx.x;
    int cnt = g_cnt[r];
    int off = g_off[r];
    float a0 = 0.f, a1 = 0.f, a2 = 0.f, a3 = 0.f;
    int i = 0;
    for (; i + 4 <= cnt; i += 4) {
        int n0 = g_nlist[off+i],   n1 = g_nlist[off+i+1];
        int n2 = g_nlist[off+i+2], n3 = g_nlist[off+i+3];
        a0 += __ldg(&H[(size_t)n0*DD + d]);
        a1 += __ldg(&H[(size_t)n1*DD + d]);
        a2 += __ldg(&H[(size_t)n2*DD + d]);
        a3 += __ldg(&H[(size_t)n3*DD + d]);
    }
    for (; i < cnt; i++) a0 += __ldg(&H[(size_t)g_nlist[off+i]*DD + d]);
    float sum = (a0 + a1) + (a2 + a3);
    float inv = (cnt > 0) ? (1.0f / (float)cnt) : 0.0f;
    g_x[(size_t)r*DD + d] = sum * inv;
}

// ---------------- weight prep (also zeroes g_cnt) ----------------
__global__ void k_prep_w(const float* __restrict__ Wq, const float* __restrict__ Wk,
                         const float* __restrict__ Wv, const float* __restrict__ bq,
                         const float* __restrict__ bk, const float* __restrict__ bv,
                         const float* __restrict__ Wo, const float* __restrict__ fW1,
                         const float* __restrict__ fW2, const float* __restrict__ mW1,
                         const float* __restrict__ mW2) {
    int r = blockIdx.x, t = threadIdx.x;
    if (r < 8) g_cnt[r*256 + t] = 0;
    if (r < 768) {
        int n = r;
        float v = (n < 256) ? Wq[t*DD + n] : (n < 512) ? Wk[t*DD + (n-256)] : Wv[t*DD + (n-512)];
        __nv_bfloat16 h = __float2bfloat16(v);
        g_wqkvh[n*DD + t] = h;
        g_wqkvl[n*DD + t] = __float2bfloat16(v - __bfloat162float(h));
        if (t == 0) g_bqkv[n] = (n < 256) ? bq[n] : (n < 512) ? bk[n-256] : bv[n-512];
    } else if (r < 1024) {
        int n = r - 768;
        float v = Wo[t*DD + n];
        __nv_bfloat16 h = __float2bfloat16(v);
        g_woh[n*DD + t] = h;
        g_wol[n*DD + t] = __float2bfloat16(v - __bfloat162float(h));
    } else if (r < 2048) {
        int n = r - 1024;
        float v = fW1[t*FF + n];
        __nv_bfloat16 h = __float2bfloat16(v);
        g_f1h[n*DD + t] = h;
        g_f1l[n*DD + t] = __float2bfloat16(v - __bfloat162float(h));
    } else if (r < 2304) {
        int n = r - 2048;
        #pragma unroll
        for (int kk = 0; kk < 4; kk++) {
            int k = t + kk*256;
            float v = fW2[k*DD + n];
            __nv_bfloat16 h = __float2bfloat16(v);
            g_f2h[n*FF + k] = h;
            g_f2l[n*FF + k] = __float2bfloat16(v - __bfloat162float(h));
        }
    } else if (r < 2560) {
        int n = r - 2304;
        float v = mW1[(256 + t)*DD + n];
        __nv_bfloat16 h = __float2bfloat16(v);
        g_p2h[n*DD + t] = h;
        g_p2l[n*DD + t] = __float2bfloat16(v - __bfloat162float(h));
    } else if (r < 2816) {
        int n = r - 2560;
        g_w1f[n*DD + t] = __float2half(mW1[t*DD + n]);
    } else {
        int n = r - 2816;
        float v = mW2[t*DD + n];
        __half h = __float2half(v);
        g_w2fh[n*DD + t] = h;
        g_w2fl[n*DD + t] = __float2half(v - __half2float(h));
    }
}

// ---------------- layer norm ----------------
__global__ void k_ln(const float* __restrict__ in, const float* __restrict__ gw,
                     const float* __restrict__ bw, float* __restrict__ out) {
    int r = blockIdx.x, d = threadIdx.x;
    float v = in[(size_t)r*DD + d];
    __shared__ float s1[8], s2[8];
    __shared__ float smu, sri;
    float a = v, b = v * v;
    #pragma unroll
    for (int o = 16; o > 0; o >>= 1) {
        a += __shfl_down_sync(0xffffffffu, a, o);
        b += __shfl_down_sync(0xffffffffu, b, o);
    }
    if ((d & 31) == 0) { s1[d >> 5] = a; s2[d >> 5] = b; }
    __syncthreads();
    if (d == 0) {
        float sa = 0.f, sb = 0.f;
        #pragma unroll
        for (int i = 0; i < 8; i++) { sa += s1[i]; sb += s2[i]; }
        float m   = sa * (1.0f / DD);
        float var = sb * (1.0f / DD) - m * m;
        smu = m; sri = rsqrtf(var + 1e-5f);
    }
    __syncthreads();
    out[(size_t)r*DD + d] = (v - smu) * sri * gw[d] + bw[d];
}

__global__ __launch_bounds__(256) void k_kvsum() {
    int b = blockIdx.x;
    int s = b >> 2, h = b & 3;
    int t = threadIdx.x, tx = t & 15, ty = t >> 4;
    __shared__ float ks[8][64], vs[8][64];
    float acc[4][4] = {};
    float ksl = 0.0f;
    const float* kp = g_qkv + (size_t)s*KK*QKVW + 256 + h*HDD;
    const float* vp = g_qkv + (size_t)s*KK*QKVW + 512 + h*HDD;

    for (int k0 = 0; k0 < KK; k0 += 8) {
        #pragma unroll
        for (int u = 0; u < 2; u++) {
            int idx = t + u*256; int i = idx >> 6, d = idx & 63;
            ks[i][d] = kp[(size_t)(k0 + i)*QKVW + d];
            vs[i][d] = vp[(size_t)(k0 + i)*QKVW + d];
        }
        __syncthreads();
        if (t < 64) {
            #pragma unroll
            for (int i = 0; i < 8; i++) ksl += ks[i][t];
        }
        #pragma unroll
        for (int i = 0; i < 8; i++) {
            float kd[4], ve[4];
            #pragma unroll
            for (int j = 0; j < 4; j++) { kd[j] = ks[i][ty*4+j]; ve[j] = vs[i][tx*4+j]; }
            #pragma unroll
            for (int a = 0; a < 4; a++)
                #pragma unroll
                for (int c = 0; c < 4; c++)
                    acc[a][c] += kd[a] * ve[c];
        }
        __syncthreads();
    }
    if (t < 64) g_ksum[(size_t)b*64 + t] = ksl;
    #pragma unroll
    for (int a = 0; a < 4; a++)
        #pragma unroll
        for (int c = 0; c < 4; c++)
            g_kv[((size_t)b*64 + ty*4 + a)*64 + tx*4 + c] = acc[a][c];
}

__global__ void k_attn() {
    int r = blockIdx.x;
    int s = r / KK;
    int t = threadIdx.x;
    __shared__ float qs[256];
    qs[t] = g_qkv[(size_t)r*QKVW + t];
    __syncthreads();
    int h = t >> 6, e = t & 63;
    const float* kvp = g_kv   + (size_t)(s*NHH + h)*HDD*HDD;
    const float* ksp = g_ksum + (size_t)(s*NHH + h)*HDD;
    float num = 0.f, den = 0.f;
    #pragma unroll 8
    for (int d = 0; d < 64; d++) {
        float q = qs[h*64 + d];
        num += q * kvp[d*64 + e];
        den += q * ksp[d];
    }
    g_attn[(size_t)r*DD + t] = num / (den + 1e-6f);
}

// ---- Pipelined patch GEMM (bf16x3): C = epi(A[M,Kd] @ Bt^T) ----
// modes: 0: +bias; 2: +bias+res; 5: gelu(+bias); 6: qkv epilogue
__global__ __launch_bounds__(256, 2) void k_mma_p(
    const float* __restrict__ A,
    const __nv_bfloat16* __restrict__ Bh,
    const __nv_bfloat16* __restrict__ Bl,
    float* __restrict__ C, int Kd, int Cld, int mode,
    const float* __restrict__ bias, const float* __restrict__ res)
{
    extern __shared__ char sm[];
    const uint32_t sb = smem_u32(sm);

    const int t = threadIdx.x, lane = t & 31, wid = t >> 5;
    const int n0 = blockIdx.x * 128, m0 = blockIdx.y * 128;
    const int wm = (wid & 3) * 32;
    const int wn = (wid >> 2) * 64;

    const int a_m = wm + (lane & 15);
    const int a_k = (lane >> 4) << 3;
    const int b_n = wn + ((lane >> 4) << 3) + (lane & 7);
    const int b_k = ((lane >> 3) & 1) << 3;

    const int ar = t >> 3, aq = t & 7;
    const int br = t >> 2, bq = t & 3;

    float acc[2][8][4] = {};
    const int nch = Kd >> 5;
    float4 apre[4];

    auto loadA = [&](int c) {
        const float* Ab = A + (size_t)m0*Kd + c*32;
        #pragma unroll
        for (int i = 0; i < 4; i++)
            apre[i] = *(const float4*)(Ab + (size_t)(ar + 32*i)*Kd + aq*4);
    };
    auto storeA = [&](int stg) {
        #pragma unroll
        for (int i = 0; i < 4; i++) {
            float4 f = apre[i];
            uint32_t h01 = pack_bf2(f.x, f.y);
            uint32_t h23 = pack_bf2(f.z, f.w);
            uint32_t l01 = pack_bf2(f.x - bflo(h01), f.y - bfhi(h01));
            uint32_t l23 = pack_bf2(f.z - bflo(h23), f.w - bfhi(h23));
            uint32_t eo = ((ar + 32*i)*40 + aq*4) * 2;
            *(uint2*)(sm + PSM_AH(stg) + eo) = make_uint2(h01, h23);
            *(uint2*)(sm + PSM_AL(stg) + eo) = make_uint2(l01, l23);
        }
    };
    auto loadB = [&](int c, int stg) {
        const int k0 = c * 32;
        #pragma unroll
        for (int i = 0; i < 2; i++) {
            int row = br + 64*i;
            uint32_t eo = (row*40 + bq*8) * 2;
            CP_ASYNC16(sb + PSM_BH(stg) + eo,
                       (const void*)(Bh + (size_t)(n0 + row)*Kd + k0 + bq*8));
            CP_ASYNC16(sb + PSM_BL(stg) + eo,
                       (const void*)(Bl + (size_t)(n0 + row)*Kd + k0 + bq*8));
        }
        CP_COMMIT();
    };

    loadA(0);
    loadB(0, 0);
    storeA(0);
    CP_WAIT0();
    __syncthreads();

    for (int c = 0; c < nch; c++) {
        const int cur = c & 1, nxt = cur ^ 1;
        const bool more = (c + 1 < nch);
        if (more) { loadA(c + 1); loadB(c + 1, nxt); }

        #pragma unroll
        for (int kk = 0; kk < 2; kk++) {
            uint32_t ah[2][4], al[2][4];
            #pragma unroll
            for (int mt = 0; mt < 2; mt++) {
                uint32_t eo = (uint32_t)((a_m + mt*16) * 40 + kk*16 + a_k) * 2;
                LDSM_X4(ah[mt][0], ah[mt][1], ah[mt][2], ah[mt][3], sb + PSM_AH(cur) + eo);
                LDSM_X4(al[mt][0], al[mt][1], al[mt][2], al[mt][3], sb + PSM_AL(cur) + eo);
            }
            #pragma unroll
            for (int g = 0; g < 4; g++) {
                uint32_t eo = (uint32_t)((b_n + g*16) * 40 + kk*16 + b_k) * 2;
                uint32_t bh[2][2], bl[2][2];
                LDSM_X4(bh[0][0], bh[0][1], bh[1][0], bh[1][1], sb + PSM_BH(cur) + eo);
                LDSM_X4(bl[0][0], bl[0][1], bl[1][0], bl[1][1], sb + PSM_BL(cur) + eo);
                #pragma unroll
                for (int mt = 0; mt < 2; mt++) {
                    #pragma unroll
                    for (int j = 0; j < 2; j++) {
                        float* d = acc[mt][g*2 + j];
                        MMA_BF16(d, ah[mt], bh[j]);
                        MMA_BF16(d, ah[mt], bl[j]);
                        MMA_BF16(d, al[mt], bh[j]);
                    }
                }
            }
        }
        if (more) { storeA(nxt); CP_WAIT0(); }
        __syncthreads();
    }

    const int lr = lane >> 2;
    const int lc = (lane & 3) * 2;
    #pragma unroll
    for (int mt = 0; mt < 2; mt++) {
        int mrow0 = m0 + wm + mt*16 + lr;
        int mrow1 = mrow0 + 8;
        if (mode == 2) {
            #pragma unroll
            for (int nt = 0; nt < 8; nt++) {
                int col = n0 + wn + nt*8 + lc;
                float2 bv = *(const float2*)(bias + col);
                float2 r0 = *(const float2*)(res + (size_t)mrow0*Cld + col);
                float2 r1 = *(const float2*)(res + (size_t)mrow1*Cld + col);
                float2 o0, o1;
                o0.x = acc[mt][nt][0] + bv.x + r0.x;
                o0.y = acc[mt][nt][1] + bv.y + r0.y;
                o1.x = acc[mt][nt][2] + bv.x + r1.x;
                o1.y = acc[mt][nt][3] + bv.y + r1.y;
                *(float2*)(C + (size_t)mrow0*Cld + col) = o0;
                *(float2*)(C + (size_t)mrow1*Cld + col) = o1;
            }
        } else if (mode == 5) {
            #pragma unroll
            for (int nt = 0; nt < 8; nt++) {
                int col = n0 + wn + nt*8 + lc;
                float2 bv = *(const float2*)(bias + col);
                float2 o0, o1;
                o0.x = geluf(acc[mt][nt][0] + bv.x);
                o0.y = geluf(acc[mt][nt][1] + bv.y);
                o1.x = geluf(acc[mt][nt][2] + bv.x);
                o1.y = geluf(acc[mt][nt][3] + bv.y);
                *(float2*)(C + (size_t)mrow0*Cld + col) = o0;
                *(float2*)(C + (size_t)mrow1*Cld + col) = o1;
            }
        } else if (mode == 6) {
            float mk0 = (g_cnt[mrow0] > 0) ? 1.0f : 0.0f;
            float mk1 = (g_cnt[mrow1] > 0) ? 1.0f : 0.0f;
            #pragma unroll
            for (int nt = 0; nt < 8; nt++) {
                int col = n0 + wn + nt*8 + lc;
                float2 bv = *(const float2*)(bias + col);
                float v00 = acc[mt][nt][0] + bv.x, v01 = acc[mt][nt][1] + bv.y;
                float v10 = acc[mt][nt][2] + bv.x, v11 = acc[mt][nt][3] + bv.y;
                float2 o0, o1;
                if (col < 256) {
                    o0.x = phif(v00); o0.y = phif(v01);
                    o1.x = phif(v10); o1.y = phif(v11);
                } else if (col < 512) {
                    o0.x = phif(v00) * mk0; o0.y = phif(v01) * mk0;
                    o1.x = phif(v10) * mk1; o1.y = phif(v11) * mk1;
                } else {
                    o0.x = v00 * mk0; o0.y = v01 * mk0;
                    o1.x = v10 * mk1; o1.y = v11 * mk1;
                }
                *(float2*)(C + (size_t)mrow0*Cld + col) = o0;
                *(float2*)(C + (size_t)mrow1*Cld + col) = o1;
            }
        } else { // mode 0
            #pragma unroll
            for (int nt = 0; nt < 8; nt++) {
                int col = n0 + wn + nt*8 + lc;
                float2 bv = *(const float2*)(bias + col);
                float2 o0, o1;
                o0.x = acc[mt][nt][0] + bv.x;
                o0.y = acc[mt][nt][1] + bv.y;
                o1.x = acc[mt][nt][2] + bv.x;
                o1.y = acc[mt][nt][3] + bv.y;
                *(float2*)(C + (size_t)mrow0*Cld + col) = o0;
                *(float2*)(C + (size_t)mrow1*Cld + col) = o1;
            }
        }
    }
}

// ---- Node GEMM1 (fp16 2-term): hid = gelu((Ah+Al)@W1f^T + p2[pid]) -> fp16 ----
__global__ __launch_bounds__(256, 2) void k_node1(
    const float* __restrict__ H, const float* __restrict__ p2,
    const int* __restrict__ pid)
{
    extern __shared__ char sm[];
    const uint32_t sb = smem_u32(sm);

    const int t = threadIdx.x, lane = t & 31, wid = t >> 5;
    const int n0 = blockIdx.x * 128, m0 = blockIdx.y * 128;
    const int wm = (wid & 3) * 32;
    const int wn = (wid >> 2) * 64;

    const int a_m = wm + (lane & 15);
    const int a_k = (lane >> 4) << 3;
    const int b_n = wn + ((lane >> 4) << 3) + (lane & 7);
    const int b_k = ((lane >> 3) & 1) << 3;
    const int ar = t >> 3, aq = t & 7;
    const int br = t >> 2, bq = t & 3;

    float acc[2][8][4] = {};
    float4 apre[4];

    auto loadA = [&](int c) {
        const float* Ab = H + (size_t)m0*DD + c*32;
        #pragma unroll
        for (int i = 0; i < 4; i++)
            apre[i] = *(const float4*)(Ab + (size_t)(ar + 32*i)*DD + aq*4);
    };
    auto storeA = [&](int stg) {
        #pragma unroll
        for (int i = 0; i < 4; i++) {
            float4 f = apre[i];
            uint32_t h01 = pack_hf2(f.x, f.y);
            uint32_t h23 = pack_hf2(f.z, f.w);
            uint32_t l01 = pack_hf2(f.x - hflo(h01), f.y - hfhi(h01));
            uint32_t l23 = pack_hf2(f.z - hflo(h23), f.w - hfhi(h23));
            uint32_t eo = ((ar + 32*i)*40 + aq*4) * 2;
            *(uint2*)(sm + NS_T0(stg) + eo) = make_uint2(h01, h23);
            *(uint2*)(sm + NS_T1(stg) + eo) = make_uint2(l01, l23);
        }
    };
    auto loadB = [&](int c, int stg) {
        const int k0 = c * 32;
        #pragma unroll
        for (int i = 0; i < 2; i++) {
            int row = br + 64*i;
            uint32_t eo = (row*40 + bq*8) * 2;
            CP_ASYNC16(sb + NS_T2(stg) + eo,
                       (const void*)(g_w1f + (size_t)(n0 + row)*DD + k0 + bq*8));
        }
        CP_COMMIT();
    };

    loadA(0); loadB(0, 0); storeA(0);
    CP_WAIT0();
    __syncthreads();

    for (int c = 0; c < 8; c++) {
        const int cur = c & 1, nxt = cur ^ 1;
        const bool more = (c + 1 < 8);
        if (more) { loadA(c + 1); loadB(c + 1, nxt); }

        #pragma unroll
        for (int kk = 0; kk < 2; kk++) {
            uint32_t ah[2][4], al[2][4];
            #pragma unroll
            for (int mt = 0; mt < 2; mt++) {
                uint32_t eo = (uint32_t)((a_m + mt*16) * 40 + kk*16 + a_k) * 2;
                LDSM_X4(ah[mt][0], ah[mt][1], ah[mt][2], ah[mt][3], sb + NS_T0(cur) + eo);
                LDSM_X4(al[mt][0], al[mt][1], al[mt][2], al[mt][3], sb + NS_T1(cur) + eo);
            }
            #pragma unroll
            for (int g = 0; g < 4; g++) {
                uint32_t eo = (uint32_t)((b_n + g*16) * 40 + kk*16 + b_k) * 2;
                uint32_t bh[2][2];
                LDSM_X4(bh[0][0], bh[0][1], bh[1][0], bh[1][1], sb + NS_T2(cur) + eo);
                #pragma unroll
                for (int mt = 0; mt < 2; mt++) {
                    #pragma unroll
                    for (int j = 0; j < 2; j++) {
                        float* d = acc[mt][g*2 + j];
                        MMA_F16(d, ah[mt], bh[j]);
                        MMA_F16(d, al[mt], bh[j]);
                    }
                }
            }
        }
        if (more) { storeA(nxt); CP_WAIT0(); }
        __syncthreads();
    }

    const int lr = lane >> 2;
    const int lc = (lane & 3) * 2;
    #pragma unroll
    for (int mt = 0; mt < 2; mt++) {
        int mrow0 = m0 + wm + mt*16 + lr;
        int mrow1 = mrow0 + 8;
        int s0 = mrow0 >> 15, s1 = mrow1 >> 15;
        const float* p2r0 = p2 + ((size_t)(s0*KK + pid[mrow0]))*DD;
        const float* p2r1 = p2 + ((size_t)(s1*KK + pid[mrow1]))*DD;
        #pragma unroll
        for (int nt = 0; nt < 8; nt++) {
            int col = n0 + wn + nt*8 + lc;
            float v00 = geluf(acc[mt][nt][0] + p2r0[col]);
            float v01 = geluf(acc[mt][nt][1] + p2r0[col+1]);
            float v10 = geluf(acc[mt][nt][2] + p2r1[col]);
            float v11 = geluf(acc[mt][nt][3] + p2r1[col+1]);
            *(uint32_t*)&g_hidf[(size_t)mrow0*DD + col] = pack_hf2(v00, v01);
            *(uint32_t*)&g_hidf[(size_t)mrow1*DD + col] = pack_hf2(v10, v11);
        }
    }
}

// ---- Node GEMM2 (fp16 2-term): out = hid@(W2h+W2l)^T + b2 + H ----
__global__ __launch_bounds__(256, 2) void k_node2(
    const float* __restrict__ H, const float* __restrict__ b2,
    float* __restrict__ out)
{
    extern __shared__ char sm[];
    const uint32_t sb = smem_u32(sm);

    const int t = threadIdx.x, lane = t & 31, wid = t >> 5;
    const int n0 = blockIdx.x * 128, m0 = blockIdx.y * 128;
    const int wm = (wid & 3) * 32;
    const int wn = (wid >> 2) * 64;

    const int a_m = wm + (lane & 15);
    const int a_k = (lane >> 4) << 3;
    const int b_n = wn + ((lane >> 4) << 3) + (lane & 7);
    const int b_k = ((lane >> 3) & 1) << 3;
    const int br = t >> 2, bq = t & 3;

    float acc[2][8][4] = {};

    auto loadAB = [&](int c, int stg) {
        const int k0 = c * 32;
        #pragma unroll
        for (int i = 0; i < 2; i++) {
            int row = br + 64*i;
            uint32_t eo = (row*40 + bq*8) * 2;
            CP_ASYNC16(sb + NS_T0(stg) + eo,
                       (const void*)(g_hidf + (size_t)(m0 + row)*DD + k0 + bq*8));
            CP_ASYNC16(sb + NS_T1(stg) + eo,
                       (const void*)(g_w2fh + (size_t)(n0 + row)*DD + k0 + bq*8));
            CP_ASYNC16(sb + NS_T2(stg) + eo,
                       (const void*)(g_w2fl + (size_t)(n0 + row)*DD + k0 + bq*8));
        }
        CP_COMMIT();
    };

    loadAB(0, 0);
    CP_WAIT0();
    __syncthreads();

    for (int c = 0; c < 8; c++) {
        const int cur = c & 1, nxt = cur ^ 1;
        const bool more = (c + 1 < 8);
        if (more) loadAB(c + 1, nxt);

        #pragma unroll
        for (int kk = 0; kk < 2; kk++) {
            uint32_t ah[2][4];
            #pragma unroll
            for (int mt = 0; mt < 2; mt++) {
                uint32_t eo = (uint32_t)((a_m + mt*16) * 40 + kk*16 + a_k) * 2;
                LDSM_X4(ah[mt][0], ah[mt][1], ah[mt][2], ah[mt][3], sb + NS_T0(cur) + eo);
            }
            #pragma unroll
            for (int g = 0; g < 4; g++) {
                uint32_t eo = (uint32_t)((b_n + g*16) * 40 + kk*16 + b_k) * 2;
                uint32_t bh[2][2], bl[2][2];
                LDSM_X4(bh[0][0], bh[0][1], bh[1][0], bh[1][1], sb + NS_T1(cur) + eo);
                LDSM_X4(bl[0][0], bl[0][1], bl[1][0], bl[1][1], sb + NS_T2(cur) + eo);
                #pragma unroll
                for (int mt = 0; mt < 2; mt++) {
                    #pragma unroll
                    for (int j = 0; j < 2; j++) {
                        float* d = acc[mt][g*2 + j];
                        MMA_F16(d, ah[mt], bh[j]);
                        MMA_F16(d, ah[mt], bl[j]);
                    }
                }
            }
        }
        if (more) CP_WAIT0();
        __syncthreads();
    }

    const int lr = lane >> 2;
    const int lc = (lane & 3) * 2;
    #pragma unroll
    for (int mt = 0; mt < 2; mt++) {
        int mrow0 = m0 + wm + mt*16 + lr;
        int mrow1 = mrow0 + 8;
        #pragma unroll
        for (int nt = 0; nt < 8; nt++) {
            int col = n0 + wn + nt*8 + lc;
            float2 bv = *(const float2*)(b2 + col);
            float2 r0 = *(const float2*)(H + (size_t)mrow0*DD + col);
            float2 r1 = *(const float2*)(H + (size_t)mrow1*DD + col);
            float2 o0, o1;
            o0.x = acc[mt][nt][0] + bv.x + r0.x;
            o0.y = acc[mt][nt][1] + bv.y + r0.y;
            o1.x = acc[mt][nt][2] + bv.x + r1.x;
            o1.y = acc[mt][nt][3] + bv.y + r1.y;
            *(float2*)(out + (size_t)mrow0*DD + col) = o0;
            *(float2*)(out + (size_t)mrow1*DD + col) = o1;
        }
    }
}

// ---------------- launch ----------------
extern "C" void kernel_launch(void* const* d_in, const int* in_sizes, int n_in,
                              void* d_out, int out_size) {
    (void)in_sizes; (void)n_in; (void)out_size;
    const float* H    = (const float*)d_in[0];
    const int*   pid  = (const int*)  d_in[1];
    const float* ln1g = (const float*)d_in[2];
    const float* ln1b = (const float*)d_in[3];
    const float* Wq   = (const float*)d_in[4];
    const float* bq   = (const float*)d_in[5];
    const float* Wk   = (const float*)d_in[6];
    const float* bk   = (const float*)d_in[7];
    const float* Wv   = (const float*)d_in[8];
    const float* bv   = (const float*)d_in[9];
    const float* Wo   = (const float*)d_in[10];
    const float* bo   = (const float*)d_in[11];
    const float* ln2g = (const float*)d_in[12];
    const float* ln2b = (const float*)d_in[13];
    const float* fW1  = (const float*)d_in[14];
    const float* fb1  = (const float*)d_in[15];
    const float* fW2  = (const float*)d_in[16];
    const float* fb2  = (const float*)d_in[17];
    const float* mW1  = (const float*)d_in[18];
    const float* mb1  = (const float*)d_in[19];
    const float* mW2  = (const float*)d_in[20];
    const float* mb2  = (const float*)d_in[21];

    float* out = (float*)d_out;
    float* psu = out + (size_t)SS*NN*DD;

    float *p_x, *p_y, *p_qkv, *p_attn, *p_x2, *p_h, *p_p2, *p_bqkv;
    __nv_bfloat16 *p_wqkvh, *p_wqkvl, *p_woh, *p_wol, *p_f1h, *p_f1l, *p_f2h, *p_f2l;
    __nv_bfloat16 *p_p2h, *p_p2l;
    cudaGetSymbolAddress((void**)&p_x,     g_x);
    cudaGetSymbolAddress((void**)&p_y,     g_y);
    cudaGetSymbolAddress((void**)&p_qkv,   g_qkv);
    cudaGetSymbolAddress((void**)&p_attn,  g_attn);
    cudaGetSymbolAddress((void**)&p_x2,    g_x2);
    cudaGetSymbolAddress((void**)&p_h,     g_h);
    cudaGetSymbolAddress((void**)&p_p2,    g_p2);
    cudaGetSymbolAddress((void**)&p_bqkv,  g_bqkv);
    cudaGetSymbolAddress((void**)&p_wqkvh, g_wqkvh);
    cudaGetSymbolAddress((void**)&p_wqkvl, g_wqkvl);
    cudaGetSymbolAddress((void**)&p_woh,   g_woh);
    cudaGetSymbolAddress((void**)&p_wol,   g_wol);
    cudaGetSymbolAddress((void**)&p_f1h,   g_f1h);
    cudaGetSymbolAddress((void**)&p_f1l,   g_f1l);
    cudaGetSymbolAddress((void**)&p_f2h,   g_f2h);
    cudaGetSymbolAddress((void**)&p_f2l,   g_f2l);
    cudaGetSymbolAddress((void**)&p_p2h,   g_p2h);
    cudaGetSymbolAddress((void**)&p_p2l,   g_p2l);

    static int smem_set = 0;
    if (!smem_set) {
        cudaFuncSetAttribute(k_mma_p, cudaFuncAttributeMaxDynamicSharedMemorySize, PSM_TOTAL);
        cudaFuncSetAttribute(k_node1, cudaFuncAttributeMaxDynamicSharedMemorySize, NS_TOTAL);
        cudaFuncSetAttribute(k_node2, cudaFuncAttributeMaxDynamicSharedMemorySize, NS_TOTAL);
        smem_set = 1;
    }

    // 1) pooling (count-sort) + weight prep (prep also zeroes g_cnt)
    k_prep_w<<<3072, 256>>>(Wq, Wk, Wv, bq, bk, bv, Wo, fW1, fW2, mW1, mW2);
    k_count<<<SS*NN/256, 256>>>(pid);
    k_scan<<<1, 256>>>();
    k_scatter<<<SS*NN/256, 256>>>(pid);
    k_patchsum<<<SS*KK, 256>>>(H);

    // 2) patch transformer (pipelined tensor-core GEMMs, bf16x3)
    k_ln<<<SS*KK, 256>>>(p_x, ln1g, ln1b, p_y);
    k_mma_p<<<dim3(QKVW/128, (SS*KK)/128), 256, PSM_TOTAL>>>(
        p_y, p_wqkvh, p_wqkvl, p_qkv, DD, QKVW, 6, p_bqkv, nullptr);
    k_kvsum<<<SS*NHH, 256>>>();
    k_attn<<<SS*KK, 256>>>();
    k_mma_p<<<dim3(DD/128, (SS*KK)/128), 256, PSM_TOTAL>>>(
        p_attn, p_woh, p_wol, p_x2, DD, DD, 2, bo, p_x);
    k_ln<<<SS*KK, 256>>>(p_x2, ln2g, ln2b, p_y);
    k_mma_p<<<dim3(FF/128, (SS*KK)/128), 256, PSM_TOTAL>>>(
        p_y, p_f1h, p_f1l, p_h, DD, FF, 5, fb1, nullptr);
    k_mma_p<<<dim3(DD/128, (SS*KK)/128), 256, PSM_TOTAL>>>(
        p_h, p_f2h, p_f2l, psu, FF, DD, 2, fb2, p_x2);

    // 3) node MLP: p2 precompute (bf16x3), then fp16 2-term node GEMMs
    k_mma_p<<<dim3(DD/128, (SS*KK)/128), 256, PSM_TOTAL>>>(
        psu, p_p2h, p_p2l, p_p2, DD, DD, 0, mb1, nullptr);
    dim3 gb(DD/128, (SS*NN)/128);
    k_node1<<<gb, 256, NS_TOTAL>>>(H, p_p2, pid);
    k_node2<<<gb, 256, NS_TOTAL>>>(H, mb2, out);
}

// round 10
// speedup vs baseline: 1.6653x; 1.2496x over previous
#include <cuda_runtime.h>
#include <cuda_bf16.h>
#include <cuda_fp16.h>
#include <math.h>
#include <stdint.h>

// Problem constants
#define SS  4
#define NN  32768
#define DD  256
#define KK  512
#define NHH 4
#define HDD 64
#define FF  1024
#define QKVW 768

// ---------------- scratch ----------------
__device__ float g_x   [SS*KK*DD];
__device__ int   g_cnt [SS*KK];
__device__ int   g_off [SS*KK];
__device__ int   g_cur [SS*KK];
__device__ int   g_nlist[SS*NN];
__device__ float g_y   [SS*KK*DD];
__device__ float g_qkv [SS*KK*QKVW];
__device__ float g_kv  [SS*NHH*HDD*HDD];
__device__ float g_ksum[SS*NHH*HDD];
__device__ float g_attn[SS*KK*DD];
__device__ float g_x2  [SS*KK*DD];
__device__ float g_h   [SS*KK*FF];
__device__ float g_p2  [SS*KK*DD];
__device__ float g_bqkv[QKVW];
__device__ __half g_hidf[SS*NN*DD];        // node hidden, fp16

// bf16 hi/lo split weights (patch side), [n][k]
__device__ __nv_bfloat16 g_wqkvh[QKVW*DD], g_wqkvl[QKVW*DD];
__device__ __nv_bfloat16 g_woh [DD*DD],   g_wol [DD*DD];
__device__ __nv_bfloat16 g_f1h [FF*DD],   g_f1l [FF*DD];
__device__ __nv_bfloat16 g_f2h [DD*FF],   g_f2l [DD*FF];
__device__ __nv_bfloat16 g_p2h [DD*DD],   g_p2l [DD*DD];   // mW1[256:512]
// fp16 node weights, [n][k]
__device__ __half g_w1f [DD*DD];           // mW1[0:256]
__device__ __half g_w2f [DD*DD];           // mW2

// ---------------- helpers ----------------
__device__ __forceinline__ float geluf(float x) {
    return 0.5f * x * (1.0f + erff(x * 0.70710678118654752440f));
}
__device__ __forceinline__ float phif(float x) {
    return x > 0.0f ? x + 1.0f : expf(x);
}
__device__ __forceinline__ uint32_t pack_bf2(float a, float b) {
    __nv_bfloat162 t = __floats2bfloat162_rn(a, b);
    return *(uint32_t*)&t;
}
__device__ __forceinline__ float bflo(uint32_t p) {
    __nv_bfloat162 b = *(__nv_bfloat162*)&p; return __bfloat162float(b.x);
}
__device__ __forceinline__ float bfhi(uint32_t p) {
    __nv_bfloat162 b = *(__nv_bfloat162*)&p; return __bfloat162float(b.y);
}
__device__ __forceinline__ uint32_t pack_hf2(float a, float b) {
    __half2 t = __floats2half2_rn(a, b);
    return *(uint32_t*)&t;
}
__device__ __forceinline__ uint32_t smem_u32(const void* p) {
    uint32_t a;
    asm("{ .reg .u64 t; cvta.to.shared.u64 t, %1; cvt.u32.u64 %0, t; }" : "=r"(a) : "l"(p));
    return a;
}
#define LDSM_X4(r0, r1, r2, r3, addr) \
    asm volatile("ldmatrix.sync.aligned.m8n8.x4.shared.b16 {%0,%1,%2,%3}, [%4];" \
                 : "=r"(r0), "=r"(r1), "=r"(r2), "=r"(r3) : "r"(addr))
#define MMA_BF16(d, a, b) \
    asm volatile("mma.sync.aligned.m16n8k16.row.col.f32.bf16.bf16.f32 " \
                 "{%0,%1,%2,%3},{%4,%5,%6,%7},{%8,%9},{%0,%1,%2,%3};" \
                 : "+f"((d)[0]), "+f"((d)[1]), "+f"((d)[2]), "+f"((d)[3]) \
                 : "r"((a)[0]), "r"((a)[1]), "r"((a)[2]), "r"((a)[3]), \
                   "r"((b)[0]), "r"((b)[1]))
#define MMA_F16(d, a, b) \
    asm volatile("mma.sync.aligned.m16n8k16.row.col.f32.f16.f16.f32 " \
                 "{%0,%1,%2,%3},{%4,%5,%6,%7},{%8,%9},{%0,%1,%2,%3};" \
                 : "+f"((d)[0]), "+f"((d)[1]), "+f"((d)[2]), "+f"((d)[3]) \
                 : "r"((a)[0]), "r"((a)[1]), "r"((a)[2]), "r"((a)[3]), \
                   "r"((b)[0]), "r"((b)[1]))
#define CP_ASYNC16(dst, src) \
    asm volatile("cp.async.cg.shared.global [%0], [%1], 16;" :: "r"(dst), "l"(src))
#define CP_COMMIT() asm volatile("cp.async.commit_group;" ::: "memory")
#define CP_WAIT0()  asm volatile("cp.async.wait_group 0;" ::: "memory")

// patch GEMM smem: A 128x32 (hi/lo) + B 64x32 (hi/lo), 2 stages
#define QSM_AH(s) ((s)*10240)
#define QSM_AL(s) (20480 + (s)*10240)
#define QSM_BH(s) (40960 + (s)*5120)
#define QSM_BL(s) (51200 + (s)*5120)
#define QSM_TOTAL 61440

// node GEMM smem: A 128x32 fp16 + B 128x32 fp16, 2 stages
#define NS_A(s) ((s)*10240)
#define NS_B(s) (20480 + (s)*10240)
#define NS_TOTAL 40960

// ---------------- pooling ----------------
__global__ void k_count(const int* __restrict__ pid) {
    int b = blockIdx.x * blockDim.x + threadIdx.x;
    int s = b >> 15;
    atomicAdd(&g_cnt[s*KK + pid[b]], 1);
}

__global__ void k_scan() {
    __shared__ int part[256];
    int t = threadIdx.x;
    int base = t * 8;
    int loc[8];
    int sum = 0;
    #pragma unroll
    for (int i = 0; i < 8; i++) { loc[i] = sum; sum += g_cnt[base + i]; }
    part[t] = sum;
    __syncthreads();
    #pragma unroll
    for (int off = 1; off < 256; off <<= 1) {
        int v = (t >= off) ? part[t - off] : 0;
        __syncthreads();
        part[t] += v;
        __syncthreads();
    }
    int prev = (t > 0) ? part[t - 1] : 0;
    #pragma unroll
    for (int i = 0; i < 8; i++) {
        g_off[base + i] = prev + loc[i];
        g_cur[base + i] = prev + loc[i];
    }
}

__global__ void k_scatter(const int* __restrict__ pid) {
    int b = blockIdx.x * blockDim.x + threadIdx.x;
    int s = b >> 15;
    int pos = atomicAdd(&g_cur[s*KK + pid[b]], 1);
    g_nlist[pos] = b;
}

__global__ __launch_bounds__(256) void k_patchsum(const float* __restrict__ H) {
    int r = blockIdx.x;
    int d = threadIdx.x;
    int cnt = g_cnt[r];
    int off = g_off[r];
    float a0 = 0.f, a1 = 0.f, a2 = 0.f, a3 = 0.f;
    int i = 0;
    for (; i + 4 <= cnt; i += 4) {
        int n0 = g_nlist[off+i],   n1 = g_nlist[off+i+1];
        int n2 = g_nlist[off+i+2], n3 = g_nlist[off+i+3];
        a0 += __ldg(&H[(size_t)n0*DD + d]);
        a1 += __ldg(&H[(size_t)n1*DD + d]);
        a2 += __ldg(&H[(size_t)n2*DD + d]);
        a3 += __ldg(&H[(size_t)n3*DD + d]);
    }
    for (; i < cnt; i++) a0 += __ldg(&H[(size_t)g_nlist[off+i]*DD + d]);
    float sum = (a0 + a1) + (a2 + a3);
    float inv = (cnt > 0) ? (1.0f / (float)cnt) : 0.0f;
    g_x[(size_t)r*DD + d] = sum * inv;
}

// ---------------- weight prep (also zeroes g_cnt) ----------------
__global__ void k_prep_w(const float* __restrict__ Wq, const float* __restrict__ Wk,
                         const float* __restrict__ Wv, const float* __restrict__ bq,
                         const float* __restrict__ bk, const float* __restrict__ bv,
                         const float* __restrict__ Wo, const float* __restrict__ fW1,
                         const float* __restrict__ fW2, const float* __restrict__ mW1,
                         const float* __restrict__ mW2) {
    int r = blockIdx.x, t = threadIdx.x;
    if (r < 8) g_cnt[r*256 + t] = 0;
    if (r < 768) {
        int n = r;
        float v = (n < 256) ? Wq[t*DD + n] : (n < 512) ? Wk[t*DD + (n-256)] : Wv[t*DD + (n-512)];
        __nv_bfloat16 h = __float2bfloat16(v);
        g_wqkvh[n*DD + t] = h;
        g_wqkvl[n*DD + t] = __float2bfloat16(v - __bfloat162float(h));
        if (t == 0) g_bqkv[n] = (n < 256) ? bq[n] : (n < 512) ? bk[n-256] : bv[n-512];
    } else if (r < 1024) {
        int n = r - 768;
        float v = Wo[t*DD + n];
        __nv_bfloat16 h = __float2bfloat16(v);
        g_woh[n*DD + t] = h;
        g_wol[n*DD + t] = __float2bfloat16(v - __bfloat162float(h));
    } else if (r < 2048) {
        int n = r - 1024;
        float v = fW1[t*FF + n];
        __nv_bfloat16 h = __float2bfloat16(v);
        g_f1h[n*DD + t] = h;
        g_f1l[n*DD + t] = __float2bfloat16(v - __bfloat162float(h));
    } else if (r < 2304) {
        int n = r - 2048;
        #pragma unroll
        for (int kk = 0; kk < 4; kk++) {
            int k = t + kk*256;
            float v = fW2[k*DD + n];
            __nv_bfloat16 h = __float2bfloat16(v);
            g_f2h[n*FF + k] = h;
            g_f2l[n*FF + k] = __float2bfloat16(v - __bfloat162float(h));
        }
    } else if (r < 2560) {
        int n = r - 2304;
        float v = mW1[(256 + t)*DD + n];
        __nv_bfloat16 h = __float2bfloat16(v);
        g_p2h[n*DD + t] = h;
        g_p2l[n*DD + t] = __float2bfloat16(v - __bfloat162float(h));
    } else if (r < 2816) {
        int n = r - 2560;
        g_w1f[n*DD + t] = __float2half(mW1[t*DD + n]);
    } else {
        int n = r - 2816;
        g_w2f[n*DD + t] = __float2half(mW2[t*DD + n]);
    }
}

// ---------------- layer norm ----------------
__global__ void k_ln(const float* __restrict__ in, const float* __restrict__ gw,
                     const float* __restrict__ bw, float* __restrict__ out) {
    int r = blockIdx.x, d = threadIdx.x;
    float v = in[(size_t)r*DD + d];
    __shared__ float s1[8], s2[8];
    __shared__ float smu, sri;
    float a = v, b = v * v;
    #pragma unroll
    for (int o = 16; o > 0; o >>= 1) {
        a += __shfl_down_sync(0xffffffffu, a, o);
        b += __shfl_down_sync(0xffffffffu, b, o);
    }
    if ((d & 31) == 0) { s1[d >> 5] = a; s2[d >> 5] = b; }
    __syncthreads();
    if (d == 0) {
        float sa = 0.f, sb = 0.f;
        #pragma unroll
        for (int i = 0; i < 8; i++) { sa += s1[i]; sb += s2[i]; }
        float m   = sa * (1.0f / DD);
        float var = sb * (1.0f / DD) - m * m;
        smu = m; sri = rsqrtf(var + 1e-5f);
    }
    __syncthreads();
    out[(size_t)r*DD + d] = (v - smu) * sri * gw[d] + bw[d];
}

__global__ __launch_bounds__(256) void k_kvsum() {
    int b = blockIdx.x;
    int s = b >> 2, h = b & 3;
    int t = threadIdx.x, tx = t & 15, ty = t >> 4;
    __shared__ float ks[8][64], vs[8][64];
    float acc[4][4] = {};
    float ksl = 0.0f;
    const float* kp = g_qkv + (size_t)s*KK*QKVW + 256 + h*HDD;
    const float* vp = g_qkv + (size_t)s*KK*QKVW + 512 + h*HDD;

    for (int k0 = 0; k0 < KK; k0 += 8) {
        #pragma unroll
        for (int u = 0; u < 2; u++) {
            int idx = t + u*256; int i = idx >> 6, d = idx & 63;
            ks[i][d] = kp[(size_t)(k0 + i)*QKVW + d];
            vs[i][d] = vp[(size_t)(k0 + i)*QKVW + d];
        }
        __syncthreads();
        if (t < 64) {
            #pragma unroll
            for (int i = 0; i < 8; i++) ksl += ks[i][t];
        }
        #pragma unroll
        for (int i = 0; i < 8; i++) {
            float kd[4], ve[4];
            #pragma unroll
            for (int j = 0; j < 4; j++) { kd[j] = ks[i][ty*4+j]; ve[j] = vs[i][tx*4+j]; }
            #pragma unroll
            for (int a = 0; a < 4; a++)
                #pragma unroll
                for (int c = 0; c < 4; c++)
                    acc[a][c] += kd[a] * ve[c];
        }
        __syncthreads();
    }
    if (t < 64) g_ksum[(size_t)b*64 + t] = ksl;
    #pragma unroll
    for (int a = 0; a < 4; a++)
        #pragma unroll
        for (int c = 0; c < 4; c++)
            g_kv[((size_t)b*64 + ty*4 + a)*64 + tx*4 + c] = acc[a][c];
}

__global__ void k_attn() {
    int r = blockIdx.x;
    int s = r / KK;
    int t = threadIdx.x;
    __shared__ float qs[256];
    qs[t] = g_qkv[(size_t)r*QKVW + t];
    __syncthreads();
    int h = t >> 6, e = t & 63;
    const float* kvp = g_kv   + (size_t)(s*NHH + h)*HDD*HDD;
    const float* ksp = g_ksum + (size_t)(s*NHH + h)*HDD;
    float num = 0.f, den = 0.f;
    #pragma unroll 8
    for (int d = 0; d < 64; d++) {
        float q = qs[h*64 + d];
        num += q * kvp[d*64 + e];
        den += q * ksp[d];
    }
    g_attn[(size_t)r*DD + t] = num / (den + 1e-6f);
}

// ---- Pipelined patch GEMM (bf16x3), tile 128(M)x64(N), warp 32x32 ----
// modes: 0: +bias; 2: +bias+res; 5: gelu(+bias); 6: qkv epilogue
__global__ __launch_bounds__(256, 2) void k_mma_p(
    const float* __restrict__ A,
    const __nv_bfloat16* __restrict__ Bh,
    const __nv_bfloat16* __restrict__ Bl,
    float* __restrict__ C, int Kd, int Cld, int mode,
    const float* __restrict__ bias, const float* __restrict__ res)
{
    extern __shared__ char sm[];
    const uint32_t sb = smem_u32(sm);

    const int t = threadIdx.x, lane = t & 31, wid = t >> 5;
    const int n0 = blockIdx.x * 64, m0 = blockIdx.y * 128;
    const int wm = (wid & 3) * 32;
    const int wn = (wid >> 2) * 32;

    const int a_m = wm + (lane & 15);
    const int a_k = (lane >> 4) << 3;
    const int b_n = wn + ((lane >> 4) << 3) + (lane & 7);
    const int b_k = ((lane >> 3) & 1) << 3;

    const int ar = t >> 3, aq = t & 7;
    const int br = t >> 2, bq = t & 3;     // 64 rows x 4 quads = 256

    float acc[2][4][4] = {};
    const int nch = Kd >> 5;
    float4 apre[4];

    auto loadA = [&](int c) {
        const float* Ab = A + (size_t)m0*Kd + c*32;
        #pragma unroll
        for (int i = 0; i < 4; i++)
            apre[i] = *(const float4*)(Ab + (size_t)(ar + 32*i)*Kd + aq*4);
    };
    auto storeA = [&](int stg) {
        #pragma unroll
        for (int i = 0; i < 4; i++) {
            float4 f = apre[i];
            uint32_t h01 = pack_bf2(f.x, f.y);
            uint32_t h23 = pack_bf2(f.z, f.w);
            uint32_t l01 = pack_bf2(f.x - bflo(h01), f.y - bfhi(h01));
            uint32_t l23 = pack_bf2(f.z - bflo(h23), f.w - bfhi(h23));
            uint32_t eo = ((ar + 32*i)*40 + aq*4) * 2;
            *(uint2*)(sm + QSM_AH(stg) + eo) = make_uint2(h01, h23);
            *(uint2*)(sm + QSM_AL(stg) + eo) = make_uint2(l01, l23);
        }
    };
    auto loadB = [&](int c, int stg) {
        const int k0 = c * 32;
        uint32_t eo = (br*40 + bq*8) * 2;
        CP_ASYNC16(sb + QSM_BH(stg) + eo,
                   (const void*)(Bh + (size_t)(n0 + br)*Kd + k0 + bq*8));
        CP_ASYNC16(sb + QSM_BL(stg) + eo,
                   (const void*)(Bl + (size_t)(n0 + br)*Kd + k0 + bq*8));
        CP_COMMIT();
    };

    loadA(0);
    loadB(0, 0);
    storeA(0);
    CP_WAIT0();
    __syncthreads();

    for (int c = 0; c < nch; c++) {
        const int cur = c & 1, nxt = cur ^ 1;
        const bool more = (c + 1 < nch);
        if (more) { loadA(c + 1); loadB(c + 1, nxt); }

        #pragma unroll
        for (int kk = 0; kk < 2; kk++) {
            uint32_t ah[2][4], al[2][4];
            #pragma unroll
            for (int mt = 0; mt < 2; mt++) {
                uint32_t eo = (uint32_t)((a_m + mt*16) * 40 + kk*16 + a_k) * 2;
                LDSM_X4(ah[mt][0], ah[mt][1], ah[mt][2], ah[mt][3], sb + QSM_AH(cur) + eo);
                LDSM_X4(al[mt][0], al[mt][1], al[mt][2], al[mt][3], sb + QSM_AL(cur) + eo);
            }
            #pragma unroll
            for (int g = 0; g < 2; g++) {
                uint32_t eo = (uint32_t)((b_n + g*16) * 40 + kk*16 + b_k) * 2;
                uint32_t bh[2][2], bl[2][2];
                LDSM_X4(bh[0][0], bh[0][1], bh[1][0], bh[1][1], sb + QSM_BH(cur) + eo);
                LDSM_X4(bl[0][0], bl[0][1], bl[1][0], bl[1][1], sb + QSM_BL(cur) + eo);
                #pragma unroll
                for (int mt = 0; mt < 2; mt++) {
                    #pragma unroll
                    for (int j = 0; j < 2; j++) {
                        float* d = acc[mt][g*2 + j];
                        MMA_BF16(d, ah[mt], bh[j]);
                        MMA_BF16(d, ah[mt], bl[j]);
                        MMA_BF16(d, al[mt], bh[j]);
                    }
                }
            }
        }
        if (more) { storeA(nxt); CP_WAIT0(); }
        __syncthreads();
    }

    const int lr = lane >> 2;
    const int lc = (lane & 3) * 2;
    #pragma unroll
    for (int mt = 0; mt < 2; mt++) {
        int mrow0 = m0 + wm + mt*16 + lr;
        int mrow1 = mrow0 + 8;
        if (mode == 2) {
            #pragma unroll
            for (int nt = 0; nt < 4; nt++) {
                int col = n0 + wn + nt*8 + lc;
                float2 bv = *(const float2*)(bias + col);
                float2 r0 = *(const float2*)(res + (size_t)mrow0*Cld + col);
                float2 r1 = *(const float2*)(res + (size_t)mrow1*Cld + col);
                float2 o0, o1;
                o0.x = acc[mt][nt][0] + bv.x + r0.x;
                o0.y = acc[mt][nt][1] + bv.y + r0.y;
                o1.x = acc[mt][nt][2] + bv.x + r1.x;
                o1.y = acc[mt][nt][3] + bv.y + r1.y;
                *(float2*)(C + (size_t)mrow0*Cld + col) = o0;
                *(float2*)(C + (size_t)mrow1*Cld + col) = o1;
            }
        } else if (mode == 5) {
            #pragma unroll
            for (int nt = 0; nt < 4; nt++) {
                int col = n0 + wn + nt*8 + lc;
                float2 bv = *(const float2*)(bias + col);
                float2 o0, o1;
                o0.x = geluf(acc[mt][nt][0] + bv.x);
                o0.y = geluf(acc[mt][nt][1] + bv.y);
                o1.x = geluf(acc[mt][nt][2] + bv.x);
                o1.y = geluf(acc[mt][nt][3] + bv.y);
                *(float2*)(C + (size_t)mrow0*Cld + col) = o0;
                *(float2*)(C + (size_t)mrow1*Cld + col) = o1;
            }
        } else if (mode == 6) {
            float mk0 = (g_cnt[mrow0] > 0) ? 1.0f : 0.0f;
            float mk1 = (g_cnt[mrow1] > 0) ? 1.0f : 0.0f;
            #pragma unroll
            for (int nt = 0; nt < 4; nt++) {
                int col = n0 + wn + nt*8 + lc;
                float2 bv = *(const float2*)(bias + col);
                float v00 = acc[mt][nt][0] + bv.x, v01 = acc[mt][nt][1] + bv.y;
                float v10 = acc[mt][nt][2] + bv.x, v11 = acc[mt][nt][3] + bv.y;
                float2 o0, o1;
                if (col < 256) {
                    o0.x = phif(v00); o0.y = phif(v01);
                    o1.x = phif(v10); o1.y = phif(v11);
                } else if (col < 512) {
                    o0.x = phif(v00) * mk0; o0.y = phif(v01) * mk0;
                    o1.x = phif(v10) * mk1; o1.y = phif(v11) * mk1;
                } else {
                    o0.x = v00 * mk0; o0.y = v01 * mk0;
                    o1.x = v10 * mk1; o1.y = v11 * mk1;
                }
                *(float2*)(C + (size_t)mrow0*Cld + col) = o0;
                *(float2*)(C + (size_t)mrow1*Cld + col) = o1;
            }
        } else { // mode 0
            #pragma unroll
            for (int nt = 0; nt < 4; nt++) {
                int col = n0 + wn + nt*8 + lc;
                float2 bv = *(const float2*)(bias + col);
                float2 o0, o1;
                o0.x = acc[mt][nt][0] + bv.x;
                o0.y = acc[mt][nt][1] + bv.y;
                o1.x = acc[mt][nt][2] + bv.x;
                o1.y = acc[mt][nt][3] + bv.y;
                *(float2*)(C + (size_t)mrow0*Cld + col) = o0;
                *(float2*)(C + (size_t)mrow1*Cld + col) = o1;
            }
        }
    }
}

// ---- Node GEMM1 (fp16 x fp16, single term): hid = gelu(A@W1f^T + p2[pid]) -> fp16 ----
__global__ __launch_bounds__(256, 2) void k_node1(
    const float* __restrict__ H, const float* __restrict__ p2,
    const int* __restrict__ pid)
{
    extern __shared__ char sm[];
    const uint32_t sb = smem_u32(sm);

    const int t = threadIdx.x, lane = t & 31, wid = t >> 5;
    const int n0 = blockIdx.x * 128, m0 = blockIdx.y * 128;
    const int wm = (wid & 3) * 32;
    const int wn = (wid >> 2) * 64;

    const int a_m = wm + (lane & 15);
    const int a_k = (lane >> 4) << 3;
    const int b_n = wn + ((lane >> 4) << 3) + (lane & 7);
    const int b_k = ((lane >> 3) & 1) << 3;
    const int ar = t >> 3, aq = t & 7;
    const int br = t >> 2, bq = t & 3;

    float acc[2][8][4] = {};
    float4 apre[4];

    auto loadA = [&](int c) {
        const float* Ab = H + (size_t)m0*DD + c*32;
        #pragma unroll
        for (int i = 0; i < 4; i++)
            apre[i] = *(const float4*)(Ab + (size_t)(ar + 32*i)*DD + aq*4);
    };
    auto storeA = [&](int stg) {
        #pragma unroll
        for (int i = 0; i < 4; i++) {
            float4 f = apre[i];
            uint32_t h01 = pack_hf2(f.x, f.y);
            uint32_t h23 = pack_hf2(f.z, f.w);
            uint32_t eo = ((ar + 32*i)*40 + aq*4) * 2;
            *(uint2*)(sm + NS_A(stg) + eo) = make_uint2(h01, h23);
        }
    };
    auto loadB = [&](int c, int stg) {
        const int k0 = c * 32;
        #pragma unroll
        for (int i = 0; i < 2; i++) {
            int row = br + 64*i;
            uint32_t eo = (row*40 + bq*8) * 2;
            CP_ASYNC16(sb + NS_B(stg) + eo,
                       (const void*)(g_w1f + (size_t)(n0 + row)*DD + k0 + bq*8));
        }
        CP_COMMIT();
    };

    loadA(0); loadB(0, 0); storeA(0);
    CP_WAIT0();
    __syncthreads();

    for (int c = 0; c < 8; c++) {
        const int cur = c & 1, nxt = cur ^ 1;
        const bool more = (c + 1 < 8);
        if (more) { loadA(c + 1); loadB(c + 1, nxt); }

        #pragma unroll
        for (int kk = 0; kk < 2; kk++) {
            uint32_t ah[2][4];
            #pragma unroll
            for (int mt = 0; mt < 2; mt++) {
                uint32_t eo = (uint32_t)((a_m + mt*16) * 40 + kk*16 + a_k) * 2;
                LDSM_X4(ah[mt][0], ah[mt][1], ah[mt][2], ah[mt][3], sb + NS_A(cur) + eo);
            }
            #pragma unroll
            for (int g = 0; g < 4; g++) {
                uint32_t eo = (uint32_t)((b_n + g*16) * 40 + kk*16 + b_k) * 2;
                uint32_t bh[2][2];
                LDSM_X4(bh[0][0], bh[0][1], bh[1][0], bh[1][1], sb + NS_B(cur) + eo);
                #pragma unroll
                for (int mt = 0; mt < 2; mt++) {
                    #pragma unroll
                    for (int j = 0; j < 2; j++)
                        MMA_F16(acc[mt][g*2 + j], ah[mt], bh[j]);
                }
            }
        }
        if (more) { storeA(nxt); CP_WAIT0(); }
        __syncthreads();
    }

    const int lr = lane >> 2;
    const int lc = (lane & 3) * 2;
    #pragma unroll
    for (int mt = 0; mt < 2; mt++) {
        int mrow0 = m0 + wm + mt*16 + lr;
        int mrow1 = mrow0 + 8;
        int s0 = mrow0 >> 15, s1 = mrow1 >> 15;
        const float* p2r0 = p2 + ((size_t)(s0*KK + pid[mrow0]))*DD;
        const float* p2r1 = p2 + ((size_t)(s1*KK + pid[mrow1]))*DD;
        #pragma unroll
        for (int nt = 0; nt < 8; nt++) {
            int col = n0 + wn + nt*8 + lc;
            float v00 = geluf(acc[mt][nt][0] + p2r0[col]);
            float v01 = geluf(acc[mt][nt][1] + p2r0[col+1]);
            float v10 = geluf(acc[mt][nt][2] + p2r1[col]);
            float v11 = geluf(acc[mt][nt][3] + p2r1[col+1]);
            *(uint32_t*)&g_hidf[(size_t)mrow0*DD + col] = pack_hf2(v00, v01);
            *(uint32_t*)&g_hidf[(size_t)mrow1*DD + col] = pack_hf2(v10, v11);
        }
    }
}

// ---- Node GEMM2 (fp16 x fp16, single term): out = hid@W2f^T + b2 + H ----
__global__ __launch_bounds__(256, 2) void k_node2(
    const float* __restrict__ H, const float* __restrict__ b2,
    float* __restrict__ out)
{
    extern __shared__ char sm[];
    const uint32_t sb = smem_u32(sm);

    const int t = threadIdx.x, lane = t & 31, wid = t >> 5;
    const int n0 = blockIdx.x * 128, m0 = blockIdx.y * 128;
    const int wm = (wid & 3) * 32;
    const int wn = (wid >> 2) * 64;

    const int a_m = wm + (lane & 15);
    const int a_k = (lane >> 4) << 3;
    const int b_n = wn + ((lane >> 4) << 3) + (lane & 7);
    const int b_k = ((lane >> 3) & 1) << 3;
    const int br = t >> 2, bq = t & 3;

    float acc[2][8][4] = {};

    auto loadAB = [&](int c, int stg) {
        const int k0 = c * 32;
        #pragma unroll
        for (int i = 0; i < 2; i++) {
            int row = br + 64*i;
            uint32_t eo = (row*40 + bq*8) * 2;
            CP_ASYNC16(sb + NS_A(stg) + eo,
                       (const void*)(g_hidf + (size_t)(m0 + row)*DD + k0 + bq*8));
            CP_ASYNC16(sb + NS_B(stg) + eo,
                       (const void*)(g_w2f + (size_t)(n0 + row)*DD + k0 + bq*8));
        }
        CP_COMMIT();
    };

    loadAB(0, 0);
    CP_WAIT0();
    __syncthreads();

    for (int c = 0; c < 8; c++) {
        const int cur = c & 1, nxt = cur ^ 1;
        const bool more = (c + 1 < 8);
        if (more) loadAB(c + 1, nxt);

        #pragma unroll
        for (int kk = 0; kk < 2; kk++) {
            uint32_t ah[2][4];
            #pragma unroll
            for (int mt = 0; mt < 2; mt++) {
                uint32_t eo = (uint32_t)((a_m + mt*16) * 40 + kk*16 + a_k) * 2;
                LDSM_X4(ah[mt][0], ah[mt][1], ah[mt][2], ah[mt][3], sb + NS_A(cur) + eo);
            }
            #pragma unroll
            for (int g = 0; g < 4; g++) {
                uint32_t eo = (uint32_t)((b_n + g*16) * 40 + kk*16 + b_k) * 2;
                uint32_t bh[2][2];
                LDSM_X4(bh[0][0], bh[0][1], bh[1][0], bh[1][1], sb + NS_B(cur) + eo);
                #pragma unroll
                for (int mt = 0; mt < 2; mt++) {
                    #pragma unroll
                    for (int j = 0; j < 2; j++)
                        MMA_F16(acc[mt][g*2 + j], ah[mt], bh[j]);
                }
            }
        }
        if (more) CP_WAIT0();
        __syncthreads();
    }

    const int lr = lane >> 2;
    const int lc = (lane & 3) * 2;
    #pragma unroll
    for (int mt = 0; mt < 2; mt++) {
        int mrow0 = m0 + wm + mt*16 + lr;
        int mrow1 = mrow0 + 8;
        #pragma unroll
        for (int nt = 0; nt < 8; nt++) {
            int col = n0 + wn + nt*8 + lc;
            float2 bv = *(const float2*)(b2 + col);
            float2 r0 = *(const float2*)(H + (size_t)mrow0*DD + col);
            float2 r1 = *(const float2*)(H + (size_t)mrow1*DD + col);
            float2 o0, o1;
            o0.x = acc[mt][nt][0] + bv.x + r0.x;
            o0.y = acc[mt][nt][1] + bv.y + r0.y;
            o1.x = acc[mt][nt][2] + bv.x + r1.x;
            o1.y = acc[mt][nt][3] + bv.y + r1.y;
            *(float2*)(out + (size_t)mrow0*DD + col) = o0;
            *(float2*)(out + (size_t)mrow1*DD + col) = o1;
        }
    }
}

// ---------------- launch ----------------
extern "C" void kernel_launch(void* const* d_in, const int* in_sizes, int n_in,
                              void* d_out, int out_size) {
    (void)in_sizes; (void)n_in; (void)out_size;
    const float* H    = (const float*)d_in[0];
    const int*   pid  = (const int*)  d_in[1];
    const float* ln1g = (const float*)d_in[2];
    const float* ln1b = (const float*)d_in[3];
    const float* Wq   = (const float*)d_in[4];
    const float* bq   = (const float*)d_in[5];
    const float* Wk   = (const float*)d_in[6];
    const float* bk   = (const float*)d_in[7];
    const float* Wv   = (const float*)d_in[8];
    const float* bv   = (const float*)d_in[9];
    const float* Wo   = (const float*)d_in[10];
    const float* bo   = (const float*)d_in[11];
    const float* ln2g = (const float*)d_in[12];
    const float* ln2b = (const float*)d_in[13];
    const float* fW1  = (const float*)d_in[14];
    const float* fb1  = (const float*)d_in[15];
    const float* fW2  = (const float*)d_in[16];
    const float* fb2  = (const float*)d_in[17];
    const float* mW1  = (const float*)d_in[18];
    const float* mb1  = (const float*)d_in[19];
    const float* mW2  = (const float*)d_in[20];
    const float* mb2  = (const float*)d_in[21];

    float* out = (float*)d_out;
    float* psu = out + (size_t)SS*NN*DD;

    float *p_x, *p_y, *p_qkv, *p_attn, *p_x2, *p_h, *p_p2, *p_bqkv;
    __nv_bfloat16 *p_wqkvh, *p_wqkvl, *p_woh, *p_wol, *p_f1h, *p_f1l, *p_f2h, *p_f2l;
    __nv_bfloat16 *p_p2h, *p_p2l;
    cudaGetSymbolAddress((void**)&p_x,     g_x);
    cudaGetSymbolAddress((void**)&p_y,     g_y);
    cudaGetSymbolAddress((void**)&p_qkv,   g_qkv);
    cudaGetSymbolAddress((void**)&p_attn,  g_attn);
    cudaGetSymbolAddress((void**)&p_x2,    g_x2);
    cudaGetSymbolAddress((void**)&p_h,     g_h);
    cudaGetSymbolAddress((void**)&p_p2,    g_p2);
    cudaGetSymbolAddress((void**)&p_bqkv,  g_bqkv);
    cudaGetSymbolAddress((void**)&p_wqkvh, g_wqkvh);
    cudaGetSymbolAddress((void**)&p_wqkvl, g_wqkvl);
    cudaGetSymbolAddress((void**)&p_woh,   g_woh);
    cudaGetSymbolAddress((void**)&p_wol,   g_wol);
    cudaGetSymbolAddress((void**)&p_f1h,   g_f1h);
    cudaGetSymbolAddress((void**)&p_f1l,   g_f1l);
    cudaGetSymbolAddress((void**)&p_f2h,   g_f2h);
    cudaGetSymbolAddress((void**)&p_f2l,   g_f2l);
    cudaGetSymbolAddress((void**)&p_p2h,   g_p2h);
    cudaGetSymbolAddress((void**)&p_p2l,   g_p2l);

    static int smem_set = 0;
    if (!smem_set) {
        cudaFuncSetAttribute(k_mma_p, cudaFuncAttributeMaxDynamicSharedMemorySize, QSM_TOTAL);
        cudaFuncSetAttribute(k_node1, cudaFuncAttributeMaxDynamicSharedMemorySize, NS_TOTAL);
        cudaFuncSetAttribute(k_node2, cudaFuncAttributeMaxDynamicSharedMemorySize, NS_TOTAL);
        smem_set = 1;
    }

    // 1) pooling (count-sort) + weight prep
    k_prep_w<<<3072, 256>>>(Wq, Wk, Wv, bq, bk, bv, Wo, fW1, fW2, mW1, mW2);
    k_count<<<SS*NN/256, 256>>>(pid);
    k_scan<<<1, 256>>>();
    k_scatter<<<SS*NN/256, 256>>>(pid);
    k_patchsum<<<SS*KK, 256>>>(H);

    // 2) patch transformer (pipelined tensor-core GEMMs, bf16x3, N-tile 64)
    k_ln<<<SS*KK, 256>>>(p_x, ln1g, ln1b, p_y);
    k_mma_p<<<dim3(QKVW/64, (SS*KK)/128), 256, QSM_TOTAL>>>(
        p_y, p_wqkvh, p_wqkvl, p_qkv, DD, QKVW, 6, p_bqkv, nullptr);
    k_kvsum<<<SS*NHH, 256>>>();
    k_attn<<<SS*KK, 256>>>();
    k_mma_p<<<dim3(DD/64, (SS*KK)/128), 256, QSM_TOTAL>>>(
        p_attn, p_woh, p_wol, p_x2, DD, DD, 2, bo, p_x);
    k_ln<<<SS*KK, 256>>>(p_x2, ln2g, ln2b, p_y);
    k_mma_p<<<dim3(FF/64, (SS*KK)/128), 256, QSM_TOTAL>>>(
        p_y, p_f1h, p_f1l, p_h, DD, FF, 5, fb1, nullptr);
    k_mma_p<<<dim3(DD/64, (SS*KK)/128), 256, QSM_TOTAL>>>(
        p_h, p_f2h, p_f2l, psu, FF, DD, 2, fb2, p_x2);

    // 3) node MLP: p2 precompute (bf16x3), then fp16 single-term node GEMMs
    k_mma_p<<<dim3(DD/64, (SS*KK)/128), 256, QSM_TOTAL>>>(
        psu, p_p2h, p_p2l, p_p2, DD, DD, 0, mb1, nullptr);
    dim3 gb(DD/128, (SS*NN)/128);
    k_node1<<<gb, 256, NS_TOTAL>>>(H, p_p2, pid);
    k_node2<<<gb, 256, NS_TOTAL>>>(H, mb2, out);
}